// round 1
// baseline (speedup 1.0000x reference)
#include <cuda_runtime.h>
#include <cuda_bf16.h>

// ---------------- problem constants ----------------
#define BATCH   4096
#define LSEQ    50      // x length
#define CIN     128     // x channels
#define CO1     50      // conv1 out channels
#define K1      9
#define LO1     42      // 50-9+1
#define KKTOT   1152    // 128*9
#define CHUNK   384     // K-chunk staged in smem (3 chunks)
#define CH2     64      // pconv out channels
#define CI2     42
#define K2      3
#define LO2     48      // 50-3+1
#define NCAPS   384
#define NO      5
#define DIMD    16
#define PAIRS   1920    // NO*NCAPS

// ---------------- smem layout (floats) ----------------
#define X_OFF     0            // 50 x 132 (padded)   -- phase 1 only
#define X_STRIDE  132
#define WS_OFF    6600         // 50 x 388 (padded)   -- phase 1 only
#define WS_STRIDE 388
#define UHAT_OFF  0            // 1920 x 17 (overlays X/WS after conv)
#define UH_STRIDE 17
#define H_OFF     32640        // 50 x 44
#define H_STRIDE  44
#define U_OFF     34840        // 384 x 9
#define U_STRIDE  9
#define BB_OFF    38296        // 1920
#define CC_OFF    40216        // 1920
#define S_OFF     42136        // 80
#define SC_OFF    42216        // 8
#define V_OFF     42224        // 80
#define PWR_OFF   42304        // 64 x 132 (padded)
#define PWR_STRIDE 132
#define SMEM_FLOATS 50752
#define SMEM_BYTES  (SMEM_FLOATS * 4)

// reordered weights (scratch; device globals per harness rules)
__device__ float g_wrT[CO1 * KKTOT];   // [co][k*128+ci]
__device__ float g_pwr[CH2 * 128];     // [ch][k*42+ci], zero padded to 128

// ---------------- prologue: weight reorder ----------------
__global__ void reorder_weights(const float* __restrict__ w1,
                                const float* __restrict__ w2) {
    int i = blockIdx.x * 256 + threadIdx.x;
    if (i < CO1 * KKTOT) {
        int co = i / KKTOT, kk = i % KKTOT;
        int k = kk >> 7, ci = kk & 127;
        g_wrT[i] = w1[co * KKTOT + ci * K1 + k];
    }
    if (i < CH2 * 128) {
        int ch = i >> 7, j = i & 127;
        float v = 0.f;
        if (j < CI2 * K2) {
            int k = j / CI2, ci = j % CI2;
            v = w2[ch * (CI2 * K2) + ci * K2 + k];
        }
        g_pwr[i] = v;
    }
}

// ---------------- fused main kernel: 1 block = 1 sample ----------------
__global__ __launch_bounds__(512, 1)
void caps_main(const float* __restrict__ x,
               const float* __restrict__ c1b,
               const float* __restrict__ p2b,
               const float* __restrict__ W,
               float* __restrict__ out) {
    extern __shared__ float S[];
    const int b   = blockIdx.x;
    const int tid = threadIdx.x;
    const int lane = tid & 31;
    const int warp = tid >> 5;

    // ---- phase 0: load x into padded smem; load pconv weights ----
    const float4* xb = (const float4*)(x + (size_t)b * (LSEQ * CIN));
    for (int i = tid; i < (LSEQ * CIN) / 4; i += 512) {
        float4 v = __ldg(xb + i);
        int l = i >> 5, c4 = i & 31;                 // 32 float4 per row of 128
        *(float4*)&S[X_OFF + l * X_STRIDE + c4 * 4] = v;
    }
    for (int i = tid; i < CH2 * 128; i += 512) {
        int ch = i >> 7, j = i & 127;
        S[PWR_OFF + ch * PWR_STRIDE + j] = g_pwr[i];
    }
    for (int i = tid; i < PAIRS; i += 512) S[BB_OFF + i] = 0.f;

    // ---- phase 1: conv1 as GEMM [50 x 1152] * columns of x ----
    // 280 active threads: kh (k-split 2) x tco(10) x tl(14); tile 5co x 3l
    const bool act = tid < 280;
    const int kh  = tid / 140;
    const int r   = tid % 140;
    const int tco = r / 14;          // 0..9  -> co = tco*5 + jc
    const int tl  = r % 14;          // 0..13 -> l  = tl + 14*jl
    float acc[5][3];
    #pragma unroll
    for (int a = 0; a < 5; a++)
        #pragma unroll
        for (int c = 0; c < 3; c++) acc[a][c] = 0.f;

    for (int ch = 0; ch < 3; ch++) {
        __syncthreads();   // protect ws region before overwrite (and x stores 1st iter)
        // stage ws chunk: 50 rows x 384 floats
        for (int i = tid; i < CO1 * (CHUNK / 4); i += 512) {
            int co = i / (CHUNK / 4), q = i % (CHUNK / 4);
            float4 v = __ldg((const float4*)&g_wrT[co * KKTOT + ch * CHUNK + q * 4]);
            *(float4*)&S[WS_OFF + co * WS_STRIDE + q * 4] = v;
        }
        __syncthreads();
        if (act) {
            const int ckbeg = kh * 192, ckend = ckbeg + 192;
            #pragma unroll 2
            for (int ck = ckbeg; ck < ckend; ck += 4) {
                int kk = ch * CHUNK + ck;
                int xadj = kk + 4 * (kk >> 7);   // padded-row adjustment
                float4 wv[5], xv[3];
                #pragma unroll
                for (int jc = 0; jc < 5; jc++)
                    wv[jc] = *(float4*)&S[WS_OFF + (tco * 5 + jc) * WS_STRIDE + ck];
                #pragma unroll
                for (int jl = 0; jl < 3; jl++)
                    xv[jl] = *(float4*)&S[X_OFF + (tl + 14 * jl) * X_STRIDE + xadj];
                #pragma unroll
                for (int jc = 0; jc < 5; jc++) {
                    float4 w = wv[jc];
                    #pragma unroll
                    for (int jl = 0; jl < 3; jl++) {
                        float4 xx = xv[jl];
                        acc[jc][jl] += w.x * xx.x + w.y * xx.y + w.z * xx.z + w.w * xx.w;
                    }
                }
            }
        }
    }
    __syncthreads();
    // k-split reduce + bias + relu into h_s[co][l]
    if (act && kh == 0) {
        #pragma unroll
        for (int jc = 0; jc < 5; jc++) {
            int co = tco * 5 + jc;
            #pragma unroll
            for (int jl = 0; jl < 3; jl++)
                S[H_OFF + co * H_STRIDE + (tl + 14 * jl)] = acc[jc][jl];
        }
    }
    __syncthreads();
    if (act && kh == 1) {
        #pragma unroll
        for (int jc = 0; jc < 5; jc++) {
            int co = tco * 5 + jc;
            float bias = __ldg(&c1b[co]);
            #pragma unroll
            for (int jl = 0; jl < 3; jl++) {
                int l = tl + 14 * jl;
                float v = S[H_OFF + co * H_STRIDE + l] + acc[jc][jl] + bias;
                S[H_OFF + co * H_STRIDE + l] = v > 0.f ? v : 0.f;
            }
        }
    }
    __syncthreads();

    // ---- phase 2: pconv (64 x 48) + reshape + squash -> u[384][8] ----
    {
        const int ch = tid >> 3;       // 0..63
        const int pq = tid & 7;        // 0..7 -> pos tile [pq*6, pq*6+6)
        float pa[6] = {0, 0, 0, 0, 0, 0};
        #pragma unroll
        for (int k = 0; k < K2; k++) {
            const int wbase = PWR_OFF + ch * PWR_STRIDE + k * CI2;
            const int hbase = H_OFF + (pq * 6 + k) * H_STRIDE;
            for (int ci = 0; ci < CI2; ci++) {
                float w = S[wbase + ci];
                #pragma unroll
                for (int j = 0; j < 6; j++)
                    pa[j] += w * S[hbase + j * H_STRIDE + ci];
            }
        }
        float pb = __ldg(&p2b[ch]);
        #pragma unroll
        for (int j = 0; j < 6; j++) {
            int pos = pq * 6 + j;
            int lin = ch * LO2 + pos;
            S[U_OFF + (lin >> 3) * U_STRIDE + (lin & 7)] = pa[j] + pb;
        }
    }
    __syncthreads();
    if (tid < NCAPS) {
        float vv[8], sq = 0.f;
        #pragma unroll
        for (int i = 0; i < 8; i++) { vv[i] = S[U_OFF + tid * U_STRIDE + i]; sq += vv[i] * vv[i]; }
        float sc = sq / ((1.f + sq) * (sqrtf(sq) + 1e-8f));
        #pragma unroll
        for (int i = 0; i < 8; i++) S[U_OFF + tid * U_STRIDE + i] = vv[i] * sc;
    }
    __syncthreads();

    // ---- phase 3: u_hat[o,c,d] = sum_i W[o,c,d,i] * u[c,i]  (overlays X/WS) ----
    for (int p = tid; p < PAIRS; p += 512) {
        int c = p % NCAPS;
        float u8[8];
        #pragma unroll
        for (int i = 0; i < 8; i++) u8[i] = S[U_OFF + c * U_STRIDE + i];
        const float* wp = W + (size_t)p * 128;
        #pragma unroll 4
        for (int d = 0; d < DIMD; d++) {
            float4 a0 = __ldg((const float4*)(wp + d * 8));
            float4 a1 = __ldg((const float4*)(wp + d * 8 + 4));
            float s = a0.x * u8[0] + a0.y * u8[1] + a0.z * u8[2] + a0.w * u8[3]
                    + a1.x * u8[4] + a1.y * u8[5] + a1.z * u8[6] + a1.w * u8[7];
            S[UHAT_OFF + p * UH_STRIDE + d] = s;
        }
    }
    __syncthreads();

    // ---- phase 4: dynamic routing (3 rounds: 2 updates + final) ----
    for (int it = 0; it < 3; it++) {
        // softmax over o for each capsule c
        if (tid < NCAPS) {
            float bv[NO], m = -1e30f;
            #pragma unroll
            for (int o = 0; o < NO; o++) { bv[o] = S[BB_OFF + o * NCAPS + tid]; m = fmaxf(m, bv[o]); }
            float sum = 0.f;
            #pragma unroll
            for (int o = 0; o < NO; o++) { bv[o] = expf(bv[o] - m); sum += bv[o]; }
            float inv = 1.f / sum;
            #pragma unroll
            for (int o = 0; o < NO; o++) S[CC_OFF + o * NCAPS + tid] = bv[o] * inv;
        }
        __syncthreads();
        // s[o][d] = sum_c c[o,c] * uhat[o,c,d]  (warp-per-(o,d)-combo)
        for (int comb = warp; comb < NO * DIMD; comb += 16) {
            int o = comb >> 4, d = comb & 15;
            float a = 0.f;
            #pragma unroll 4
            for (int c = lane; c < NCAPS; c += 32)
                a += S[CC_OFF + o * NCAPS + c] * S[UHAT_OFF + (o * NCAPS + c) * UH_STRIDE + d];
            #pragma unroll
            for (int off = 16; off; off >>= 1) a += __shfl_xor_sync(0xffffffffu, a, off);
            if (lane == 0) S[S_OFF + comb] = a;
        }
        __syncthreads();
        // squash scale per o
        if (tid < NO) {
            float sq = 0.f;
            #pragma unroll
            for (int d = 0; d < DIMD; d++) { float t = S[S_OFF + tid * DIMD + d]; sq += t * t; }
            S[SC_OFF + tid] = sq / ((1.f + sq) * (sqrtf(sq) + 1e-8f));
        }
        __syncthreads();
        if (it == 2) break;   // final v is written below
        if (tid < NO * DIMD) S[V_OFF + tid] = S[S_OFF + tid] * S[SC_OFF + (tid >> 4)];
        __syncthreads();
        // b[o,c] += sum_d uhat[o,c,d] * v[o,d]
        for (int p = tid; p < PAIRS; p += 512) {
            int o = p / NCAPS;
            float a = 0.f;
            #pragma unroll
            for (int d = 0; d < DIMD; d++)
                a += S[UHAT_OFF + p * UH_STRIDE + d] * S[V_OFF + o * DIMD + d];
            S[BB_OFF + p] += a;
        }
        __syncthreads();
    }
    // final v -> out[b, o, d]
    if (tid < NO * DIMD)
        out[(size_t)b * (NO * DIMD) + tid] = S[S_OFF + tid] * S[SC_OFF + (tid >> 4)];
}

// ---------------- launch ----------------
extern "C" void kernel_launch(void* const* d_in, const int* in_sizes, int n_in,
                              void* d_out, int out_size) {
    const float* x       = (const float*)d_in[0];
    const float* conv1_w = (const float*)d_in[1];
    const float* conv1_b = (const float*)d_in[2];
    const float* pconv_w = (const float*)d_in[3];
    const float* pconv_b = (const float*)d_in[4];
    const float* W       = (const float*)d_in[5];
    float* out = (float*)d_out;

    cudaFuncSetAttribute(caps_main, cudaFuncAttributeMaxDynamicSharedMemorySize, SMEM_BYTES);

    reorder_weights<<<(CO1 * KKTOT + 255) / 256, 256>>>(conv1_w, pconv_w);
    caps_main<<<BATCH, 512, SMEM_BYTES>>>(x, conv1_b, pconv_b, W, out);
}

// round 2
// speedup vs baseline: 1.2226x; 1.2226x over previous
#include <cuda_runtime.h>
#include <cuda_bf16.h>

// ---------------- problem constants ----------------
#define BATCH   4096
#define LSEQ    50      // x length
#define CIN     128     // x channels
#define CO1     50      // conv1 out channels
#define K1      9
#define LO1     42      // 50-9+1
#define KKTOT   1152    // 128*9
#define KC      192     // K-chunk for conv weights in smem (6 chunks)
#define WPADN   72      // padded N (co) stride for conv weights
#define CH2     64      // pconv out channels
#define CI2     42
#define K2      3
#define LO2     48      // 50-3+1
#define NCAPS   384
#define NO      5
#define DIMD    16
#define PAIRS   1920    // NO*NCAPS

// ---------------- smem layout (floats) ----------------
// overlay region [0, 32640): phase1 = X + weight chunk; phase3+ = uhat
#define X_OFF     0            // 56 x 132 (rows 50..55 zero-pad)
#define X_STRIDE  132
#define WCH_OFF   7392         // 192 x 72 weight chunk
#define UHAT_OFF  0            // 1920 x 17
#define UH_STRIDE 17
#define H_OFF     32640        // 50 x 44  (h[co][l])
#define H_STRIDE  44
#define U_OFF     34840        // 384 x 9
#define U_STRIDE  9
#define BB_OFF    38296        // 1920
#define CC_OFF    40216        // 1920
#define S_OFF     42136        // 80
#define SC_OFF    42216        // 8
#define V_OFF     42224        // 80
#define PWR_OFF   42304        // 64 x 132 (padded)
#define PWR_STRIDE 132
#define SMEM_FLOATS 50752
#define SMEM_BYTES  (SMEM_FLOATS * 4)

// reordered weights (device-global scratch per harness rules)
__device__ float g_wtf[KKTOT * WPADN];   // [k_lin][co padded 72], tf32-rounded
__device__ float g_pwr[CH2 * 128];       // [ch][k*42+ci], zero padded to 128

__device__ __forceinline__ float to_tf32(float x) {
    unsigned u;
    asm("cvt.rna.tf32.f32 %0, %1;" : "=r"(u) : "f"(x));
    return __uint_as_float(u);
}

__device__ __forceinline__ void mma_tf32(float c[4], unsigned a0, unsigned a1,
                                         unsigned a2, unsigned a3,
                                         unsigned b0, unsigned b1) {
    asm volatile(
        "mma.sync.aligned.m16n8k8.row.col.f32.tf32.tf32.f32 "
        "{%0,%1,%2,%3}, {%4,%5,%6,%7}, {%8,%9}, {%0,%1,%2,%3};"
        : "+f"(c[0]), "+f"(c[1]), "+f"(c[2]), "+f"(c[3])
        : "r"(a0), "r"(a1), "r"(a2), "r"(a3), "r"(b0), "r"(b1));
}

// ---------------- prologue: weight reorder ----------------
__global__ void reorder_weights(const float* __restrict__ w1,
                                const float* __restrict__ w2) {
    int i = blockIdx.x * 256 + threadIdx.x;
    if (i < KKTOT * WPADN) {
        int k = i / WPADN, n = i % WPADN;
        float v = 0.f;
        if (n < CO1) {
            int kh = k >> 7, ci = k & 127;
            v = to_tf32(w1[n * KKTOT + ci * K1 + kh]);
        }
        g_wtf[i] = v;
    }
    if (i < CH2 * 128) {
        int ch = i >> 7, j = i & 127;
        float v = 0.f;
        if (j < CI2 * K2) {
            int k = j / CI2, ci = j % CI2;
            v = w2[ch * (CI2 * K2) + ci * K2 + k];
        }
        g_pwr[i] = v;
    }
}

// ---------------- fused main kernel: 1 block = 1 sample ----------------
__global__ __launch_bounds__(512, 1)
void caps_main(const float* __restrict__ x,
               const float* __restrict__ c1b,
               const float* __restrict__ p2b,
               const float* __restrict__ W,
               float* __restrict__ out) {
    extern __shared__ float S[];
    const int b    = blockIdx.x;
    const int tid  = threadIdx.x;
    const int lane = tid & 31;
    const int warp = tid >> 5;

    // ---- phase 0: prefetch first weight chunk, stage x (tf32), misc ----
    const float4* wsrc = (const float4*)g_wtf;   // chunk ch starts at ch*3456 float4
    float4 pf[7];
    #pragma unroll
    for (int j = 0; j < 7; j++) {
        int i = tid + j * 512;
        if (i < (KC * WPADN) / 4) pf[j] = __ldg(wsrc + i);
    }

    const float4* xb = (const float4*)(x + (size_t)b * (LSEQ * CIN));
    for (int i = tid; i < (LSEQ * CIN) / 4; i += 512) {
        float4 v = __ldg(xb + i);
        v.x = to_tf32(v.x); v.y = to_tf32(v.y);
        v.z = to_tf32(v.z); v.w = to_tf32(v.w);
        int l = i >> 5, c4 = i & 31;
        *(float4*)&S[X_OFF + l * X_STRIDE + c4 * 4] = v;
    }
    // zero-pad x rows 50..55 (read by padded M tiles)
    for (int i = tid; i < 6 * X_STRIDE; i += 512)
        S[X_OFF + 50 * X_STRIDE + i] = 0.f;
    for (int i = tid; i < CH2 * 128; i += 512) {
        int ch = i >> 7, j = i & 127;
        S[PWR_OFF + ch * PWR_STRIDE + j] = g_pwr[i];
    }
    for (int i = tid; i < PAIRS; i += 512) S[BB_OFF + i] = 0.f;

    // commit chunk 0
    #pragma unroll
    for (int j = 0; j < 7; j++) {
        int i = tid + j * 512;
        if (i < (KC * WPADN) / 4) *(float4*)&S[WCH_OFF + i * 4] = pf[j];
    }
    __syncthreads();

    // ---- phase 1: conv1 via tf32 mma.sync ----
    // C[l(48), co(64)] = A[l,k] x B[k,co], K=1152. 12 warps: mt(3) x ntg(4),
    // each warp owns m16 x n16 (two m16n8 tiles).
    const int mt  = warp >> 2;        // 0..2
    const int ntg = warp & 3;         // 0..3
    const int gID = lane >> 2;        // 0..7
    const int tig = lane & 3;         // 0..3
    float acc0[4] = {0, 0, 0, 0};
    float acc1[4] = {0, 0, 0, 0};

    for (int ch = 0; ch < 6; ch++) {
        if (ch < 5) {   // prefetch next chunk (overlaps compute)
            #pragma unroll
            for (int j = 0; j < 7; j++) {
                int i = tid + j * 512;
                if (i < (KC * WPADN) / 4) pf[j] = __ldg(wsrc + (ch + 1) * 3456 + i);
            }
        }
        if (warp < 12) {
            #pragma unroll 4
            for (int ks = 0; ks < KC / 8; ks++) {
                int k_lin = ch * KC + ks * 8;
                int kh = k_lin >> 7, cb = k_lin & 127;
                int xbase = X_OFF + (mt * 16 + gID + kh) * X_STRIDE + cb + tig;
                unsigned a0 = __float_as_uint(S[xbase]);
                unsigned a1 = __float_as_uint(S[xbase + 8 * X_STRIDE]);
                unsigned a2 = __float_as_uint(S[xbase + 4]);
                unsigned a3 = __float_as_uint(S[xbase + 8 * X_STRIDE + 4]);
                int wb = WCH_OFF + (ks * 8 + tig) * WPADN + ntg * 16 + gID;
                unsigned b0a = __float_as_uint(S[wb]);
                unsigned b1a = __float_as_uint(S[wb + 4 * WPADN]);
                unsigned b0b = __float_as_uint(S[wb + 8]);
                unsigned b1b = __float_as_uint(S[wb + 4 * WPADN + 8]);
                mma_tf32(acc0, a0, a1, a2, a3, b0a, b1a);
                mma_tf32(acc1, a0, a1, a2, a3, b0b, b1b);
            }
        }
        __syncthreads();
        if (ch < 5) {
            #pragma unroll
            for (int j = 0; j < 7; j++) {
                int i = tid + j * 512;
                if (i < (KC * WPADN) / 4) *(float4*)&S[WCH_OFF + i * 4] = pf[j];
            }
            __syncthreads();
        }
    }
    // epilogue: bias + relu -> h[co][l]
    if (warp < 12) {
        int m_lo = mt * 16 + gID, m_hi = m_lo + 8;
        #pragma unroll
        for (int t = 0; t < 2; t++) {
            float* a = (t == 0) ? acc0 : acc1;
            int n0 = ntg * 16 + t * 8 + 2 * tig;
            if (n0 < CO1) {
                float bias = __ldg(&c1b[n0]);
                if (m_lo < LO1) S[H_OFF + n0 * H_STRIDE + m_lo] = fmaxf(a[0] + bias, 0.f);
                if (m_hi < LO1) S[H_OFF + n0 * H_STRIDE + m_hi] = fmaxf(a[2] + bias, 0.f);
            }
            int n1 = n0 + 1;
            if (n1 < CO1) {
                float bias = __ldg(&c1b[n1]);
                if (m_lo < LO1) S[H_OFF + n1 * H_STRIDE + m_lo] = fmaxf(a[1] + bias, 0.f);
                if (m_hi < LO1) S[H_OFF + n1 * H_STRIDE + m_hi] = fmaxf(a[3] + bias, 0.f);
            }
        }
    }
    __syncthreads();

    // ---- phase 2: pconv (64 x 48) + reshape + squash -> u[384][8] ----
    {
        const int ch = tid >> 3;       // 0..63
        const int pq = tid & 7;        // 0..7 -> pos tile [pq*6, pq*6+6)
        float pa[6] = {0, 0, 0, 0, 0, 0};
        #pragma unroll
        for (int k = 0; k < K2; k++) {
            const int wbase = PWR_OFF + ch * PWR_STRIDE + k * CI2;
            const int hbase = H_OFF + (pq * 6 + k) * H_STRIDE;
            for (int ci = 0; ci < CI2; ci++) {
                float w = S[wbase + ci];
                #pragma unroll
                for (int j = 0; j < 6; j++)
                    pa[j] += w * S[hbase + j * H_STRIDE + ci];
            }
        }
        float pb = __ldg(&p2b[ch]);
        #pragma unroll
        for (int j = 0; j < 6; j++) {
            int pos = pq * 6 + j;
            int lin = ch * LO2 + pos;
            S[U_OFF + (lin >> 3) * U_STRIDE + (lin & 7)] = pa[j] + pb;
        }
    }
    __syncthreads();
    if (tid < NCAPS) {
        float vv[8], sq = 0.f;
        #pragma unroll
        for (int i = 0; i < 8; i++) { vv[i] = S[U_OFF + tid * U_STRIDE + i]; sq += vv[i] * vv[i]; }
        float sc = sq / ((1.f + sq) * (sqrtf(sq) + 1e-8f));
        #pragma unroll
        for (int i = 0; i < 8; i++) S[U_OFF + tid * U_STRIDE + i] = vv[i] * sc;
    }
    __syncthreads();

    // ---- phase 3: u_hat[o,c,d] = sum_i W[o,c,d,i] * u[c,i]  (overlays X/WCH) ----
    for (int p = tid; p < PAIRS; p += 512) {
        int c = p % NCAPS;
        float u8[8];
        #pragma unroll
        for (int i = 0; i < 8; i++) u8[i] = S[U_OFF + c * U_STRIDE + i];
        const float* wp = W + (size_t)p * 128;
        #pragma unroll 4
        for (int d = 0; d < DIMD; d++) {
            float4 a0 = __ldg((const float4*)(wp + d * 8));
            float4 a1 = __ldg((const float4*)(wp + d * 8 + 4));
            float s = a0.x * u8[0] + a0.y * u8[1] + a0.z * u8[2] + a0.w * u8[3]
                    + a1.x * u8[4] + a1.y * u8[5] + a1.z * u8[6] + a1.w * u8[7];
            S[UHAT_OFF + p * UH_STRIDE + d] = s;
        }
    }
    __syncthreads();

    // ---- phase 4: dynamic routing (3 rounds: 2 updates + final) ----
    for (int it = 0; it < 3; it++) {
        if (tid < NCAPS) {
            float bv[NO], m = -1e30f;
            #pragma unroll
            for (int o = 0; o < NO; o++) { bv[o] = S[BB_OFF + o * NCAPS + tid]; m = fmaxf(m, bv[o]); }
            float sum = 0.f;
            #pragma unroll
            for (int o = 0; o < NO; o++) { bv[o] = expf(bv[o] - m); sum += bv[o]; }
            float inv = 1.f / sum;
            #pragma unroll
            for (int o = 0; o < NO; o++) S[CC_OFF + o * NCAPS + tid] = bv[o] * inv;
        }
        __syncthreads();
        for (int comb = warp; comb < NO * DIMD; comb += 16) {
            int o = comb >> 4, d = comb & 15;
            float a = 0.f;
            #pragma unroll 4
            for (int c = lane; c < NCAPS; c += 32)
                a += S[CC_OFF + o * NCAPS + c] * S[UHAT_OFF + (o * NCAPS + c) * UH_STRIDE + d];
            #pragma unroll
            for (int off = 16; off; off >>= 1) a += __shfl_xor_sync(0xffffffffu, a, off);
            if (lane == 0) S[S_OFF + comb] = a;
        }
        __syncthreads();
        if (tid < NO) {
            float sq = 0.f;
            #pragma unroll
            for (int d = 0; d < DIMD; d++) { float t = S[S_OFF + tid * DIMD + d]; sq += t * t; }
            S[SC_OFF + tid] = sq / ((1.f + sq) * (sqrtf(sq) + 1e-8f));
        }
        __syncthreads();
        if (it == 2) break;
        if (tid < NO * DIMD) S[V_OFF + tid] = S[S_OFF + tid] * S[SC_OFF + (tid >> 4)];
        __syncthreads();
        for (int p = tid; p < PAIRS; p += 512) {
            int o = p / NCAPS;
            float a = 0.f;
            #pragma unroll
            for (int d = 0; d < DIMD; d++)
                a += S[UHAT_OFF + p * UH_STRIDE + d] * S[V_OFF + o * DIMD + d];
            S[BB_OFF + p] += a;
        }
        __syncthreads();
    }
    if (tid < NO * DIMD)
        out[(size_t)b * (NO * DIMD) + tid] = S[S_OFF + tid] * S[SC_OFF + (tid >> 4)];
}

// ---------------- launch ----------------
extern "C" void kernel_launch(void* const* d_in, const int* in_sizes, int n_in,
                              void* d_out, int out_size) {
    const float* x       = (const float*)d_in[0];
    const float* conv1_w = (const float*)d_in[1];
    const float* conv1_b = (const float*)d_in[2];
    const float* pconv_w = (const float*)d_in[3];
    const float* pconv_b = (const float*)d_in[4];
    const float* W       = (const float*)d_in[5];
    float* out = (float*)d_out;

    cudaFuncSetAttribute(caps_main, cudaFuncAttributeMaxDynamicSharedMemorySize, SMEM_BYTES);

    reorder_weights<<<(KKTOT * WPADN + 255) / 256, 256>>>(conv1_w, pconv_w);
    caps_main<<<BATCH, 512, SMEM_BYTES>>>(x, conv1_b, pconv_b, W, out);
}

// round 3
// speedup vs baseline: 2.0528x; 1.6790x over previous
#include <cuda_runtime.h>
#include <cuda_bf16.h>
#include <cuda_fp16.h>

// ---------------- problem constants ----------------
#define BATCH   4096
#define LSEQ    50
#define CIN     128
#define CO1     50
#define K1      9
#define LO1     42      // 50-9+1
#define KKTOT   1152    // 128*9
#define KC      192     // conv1 weight K-chunk (6 chunks)
#define WPADN   72
#define CH2     64
#define CI2     42
#define K2      3
#define LO2     48
#define PK      144     // pconv padded K = 3*48
#define NCAPS   384
#define NO      5
#define DIMD    16
#define PAIRS   1920

// ---------------- smem layout (floats) ----------------
// overlay [0, 32640): phase1 = X + WCH; phase2 = PW2 (reuses WCH); phase3+ = UHAT
#define X_OFF     0            // 56 x 132 (rows 50..55 zero)
#define X_STRIDE  132
#define WCH_OFF   7392         // 192 x 72 conv1 weight chunk
#define PW2_OFF   7392         // 144 x 72 pconv weights (reuse)
#define UHAT_OFF  0            // 1920 x 17
#define UH_STRIDE 17
#define HP_OFF    32640        // 50 x 49  Hp[co][l], cols 42..48 zero
#define HP_STRIDE 49
#define U_OFF     35090        // 384 x 9
#define U_STRIDE  9
#define BB_OFF    38546        // 1920
#define CC_OFF    40466        // 1920
#define S_OFF     42386        // 80
#define SC_OFF    42466        // 8
#define V_OFF     42474        // 80
#define SMEM_FLOATS 42560
#define SMEM_BYTES  (SMEM_FLOATS * 4)

// device-global scratch
__device__ float  g_wtf[KKTOT * WPADN];       // conv1 w: [k_lin][co pad72], tf32
__device__ float  g_pw2[PK * WPADN];          // pconv w: [kb*48+ci][ch pad72]
__device__ __half g_Wh[NO * NCAPS * DIMD * 8];// W in fp16, same order

__device__ __forceinline__ float to_tf32(float x) {
    unsigned u;
    asm("cvt.rna.tf32.f32 %0, %1;" : "=r"(u) : "f"(x));
    return __uint_as_float(u);
}

__device__ __forceinline__ void mma_tf32(float c[4], unsigned a0, unsigned a1,
                                         unsigned a2, unsigned a3,
                                         unsigned b0, unsigned b1) {
    asm volatile(
        "mma.sync.aligned.m16n8k8.row.col.f32.tf32.tf32.f32 "
        "{%0,%1,%2,%3}, {%4,%5,%6,%7}, {%8,%9}, {%0,%1,%2,%3};"
        : "+f"(c[0]), "+f"(c[1]), "+f"(c[2]), "+f"(c[3])
        : "r"(a0), "r"(a1), "r"(a2), "r"(a3), "r"(b0), "r"(b1));
}

// ---------------- prologue: weight reorder / convert ----------------
__global__ void reorder_weights(const float* __restrict__ w1,
                                const float* __restrict__ w2,
                                const float* __restrict__ W) {
    int i = blockIdx.x * 256 + threadIdx.x;
    if (i < KKTOT * WPADN) {
        int k = i / WPADN, n = i % WPADN;
        float v = 0.f;
        if (n < CO1) {
            int kh = k >> 7, ci = k & 127;
            v = to_tf32(w1[n * KKTOT + ci * K1 + kh]);
        }
        g_wtf[i] = v;
    }
    if (i < PK * WPADN) {
        int kk = i / WPADN, ch = i % WPADN;
        int kb = kk / 48, ci = kk % 48;
        float v = 0.f;
        if (ch < CH2 && ci < CI2)
            v = to_tf32(w2[ch * (CI2 * K2) + ci * K2 + kb]);
        g_pw2[i] = v;
    }
    if (i < NO * NCAPS * DIMD * 8)
        g_Wh[i] = __float2half(W[i]);
}

// ---------------- fused main kernel: 1 block = 1 sample ----------------
__global__ __launch_bounds__(512, 1)
void caps_main(const float* __restrict__ x,
               const float* __restrict__ c1b,
               const float* __restrict__ p2b,
               float* __restrict__ out) {
    extern __shared__ float S[];
    const int b    = blockIdx.x;
    const int tid  = threadIdx.x;
    const int lane = tid & 31;
    const int warp = tid >> 5;

    // ---- phase 0: prefetch conv w chunk0, stage x (tf32), zero scratch ----
    const float4* wsrc = (const float4*)g_wtf;
    float4 pf[7];
    #pragma unroll
    for (int j = 0; j < 7; j++) {
        int i = tid + j * 512;
        if (i < (KC * WPADN) / 4) pf[j] = __ldg(wsrc + i);
    }

    const float4* xb = (const float4*)(x + (size_t)b * (LSEQ * CIN));
    for (int i = tid; i < (LSEQ * CIN) / 4; i += 512) {
        float4 v = __ldg(xb + i);
        v.x = to_tf32(v.x); v.y = to_tf32(v.y);
        v.z = to_tf32(v.z); v.w = to_tf32(v.w);
        int l = i >> 5, c4 = i & 31;
        *(float4*)&S[X_OFF + l * X_STRIDE + c4 * 4] = v;
    }
    for (int i = tid; i < 6 * X_STRIDE; i += 512)
        S[X_OFF + 50 * X_STRIDE + i] = 0.f;
    for (int i = tid; i < CO1 * HP_STRIDE; i += 512) S[HP_OFF + i] = 0.f;
    for (int i = tid; i < PAIRS; i += 512) S[BB_OFF + i] = 0.f;

    #pragma unroll
    for (int j = 0; j < 7; j++) {
        int i = tid + j * 512;
        if (i < (KC * WPADN) / 4) *(float4*)&S[WCH_OFF + i * 4] = pf[j];
    }
    __syncthreads();

    // ---- phase 1: conv1 via tf32 mma: C[l(48), co(64)] K=1152 ----
    const int mt  = warp >> 2;        // 0..2
    const int ntg = warp & 3;         // 0..3
    const int gID = lane >> 2;        // 0..7
    const int tig = lane & 3;         // 0..3
    float acc0[4] = {0, 0, 0, 0};
    float acc1[4] = {0, 0, 0, 0};

    for (int ch = 0; ch < 6; ch++) {
        if (ch < 5) {
            #pragma unroll
            for (int j = 0; j < 7; j++) {
                int i = tid + j * 512;
                if (i < (KC * WPADN) / 4) pf[j] = __ldg(wsrc + (ch + 1) * 3456 + i);
            }
        }
        if (warp < 12) {
            #pragma unroll 4
            for (int ks = 0; ks < KC / 8; ks++) {
                int k_lin = ch * KC + ks * 8;
                int kh = k_lin >> 7, cb = k_lin & 127;
                int xbase = X_OFF + (mt * 16 + gID + kh) * X_STRIDE + cb + tig;
                unsigned a0 = __float_as_uint(S[xbase]);
                unsigned a1 = __float_as_uint(S[xbase + 8 * X_STRIDE]);
                unsigned a2 = __float_as_uint(S[xbase + 4]);
                unsigned a3 = __float_as_uint(S[xbase + 8 * X_STRIDE + 4]);
                int wb = WCH_OFF + (ks * 8 + tig) * WPADN + ntg * 16 + gID;
                unsigned b0a = __float_as_uint(S[wb]);
                unsigned b1a = __float_as_uint(S[wb + 4 * WPADN]);
                unsigned b0b = __float_as_uint(S[wb + 8]);
                unsigned b1b = __float_as_uint(S[wb + 4 * WPADN + 8]);
                mma_tf32(acc0, a0, a1, a2, a3, b0a, b1a);
                mma_tf32(acc1, a0, a1, a2, a3, b0b, b1b);
            }
        }
        __syncthreads();
        if (ch < 5) {
            #pragma unroll
            for (int j = 0; j < 7; j++) {
                int i = tid + j * 512;
                if (i < (KC * WPADN) / 4) *(float4*)&S[WCH_OFF + i * 4] = pf[j];
            }
            __syncthreads();
        }
    }
    // epilogue: bias + relu -> Hp[co][l]  (co rows, l cols)
    if (warp < 12) {
        int m_lo = mt * 16 + gID, m_hi = m_lo + 8;
        #pragma unroll
        for (int t = 0; t < 2; t++) {
            float* a = (t == 0) ? acc0 : acc1;
            int n0 = ntg * 16 + t * 8 + 2 * tig;
            if (n0 < CO1) {
                float bias = __ldg(&c1b[n0]);
                if (m_lo < LO1) S[HP_OFF + n0 * HP_STRIDE + m_lo] = fmaxf(a[0] + bias, 0.f);
                if (m_hi < LO1) S[HP_OFF + n0 * HP_STRIDE + m_hi] = fmaxf(a[2] + bias, 0.f);
            }
            int n1 = n0 + 1;
            if (n1 < CO1) {
                float bias = __ldg(&c1b[n1]);
                if (m_lo < LO1) S[HP_OFF + n1 * HP_STRIDE + m_lo] = fmaxf(a[1] + bias, 0.f);
                if (m_hi < LO1) S[HP_OFF + n1 * HP_STRIDE + m_hi] = fmaxf(a[3] + bias, 0.f);
            }
        }
    }
    __syncthreads();

    // ---- phase 2: pconv via tf32 mma: C[pos(48), ch(64)] K=144 ----
    // stage pconv weights into PW2 (reuses WCH region)
    for (int i = tid; i < (PK * WPADN) / 4; i += 512) {
        float4 v = __ldg((const float4*)g_pw2 + i);
        *(float4*)&S[PW2_OFF + i * 4] = v;
    }
    __syncthreads();
    {
        float pacc0[4] = {0, 0, 0, 0};
        float pacc1[4] = {0, 0, 0, 0};
        if (warp < 12) {
            #pragma unroll
            for (int ks = 0; ks < PK / 8; ks++) {
                int k_lin = ks * 8;
                int kb = k_lin / 48, cb = k_lin % 48;
                int abase = HP_OFF + (mt * 16 + gID + kb) * HP_STRIDE + cb + tig;
                unsigned a0 = __float_as_uint(S[abase]);
                unsigned a1 = __float_as_uint(S[abase + 8 * HP_STRIDE]);
                unsigned a2 = __float_as_uint(S[abase + 4]);
                unsigned a3 = __float_as_uint(S[abase + 8 * HP_STRIDE + 4]);
                int wb = PW2_OFF + (ks * 8 + tig) * WPADN + ntg * 16 + gID;
                unsigned b0a = __float_as_uint(S[wb]);
                unsigned b1a = __float_as_uint(S[wb + 4 * WPADN]);
                unsigned b0b = __float_as_uint(S[wb + 8]);
                unsigned b1b = __float_as_uint(S[wb + 4 * WPADN + 8]);
                mma_tf32(pacc0, a0, a1, a2, a3, b0a, b1a);
                mma_tf32(pacc1, a0, a1, a2, a3, b0b, b1b);
            }
            // epilogue: u[lin/8][lin%8] = C[pos,ch] + bias,  lin = ch*48 + pos
            int m_lo = mt * 16 + gID, m_hi = m_lo + 8;
            #pragma unroll
            for (int t = 0; t < 2; t++) {
                float* a = (t == 0) ? pacc0 : pacc1;
                #pragma unroll
                for (int q = 0; q < 2; q++) {
                    int n = ntg * 16 + t * 8 + 2 * tig + q;
                    float bias = __ldg(&p2b[n]);
                    int lin0 = n * LO2 + m_lo;
                    int lin1 = n * LO2 + m_hi;
                    S[U_OFF + (lin0 >> 3) * U_STRIDE + (lin0 & 7)] = a[q] + bias;
                    S[U_OFF + (lin1 >> 3) * U_STRIDE + (lin1 & 7)] = a[q + 2] + bias;
                }
            }
        }
    }
    __syncthreads();
    if (tid < NCAPS) {
        float vv[8], sq = 0.f;
        #pragma unroll
        for (int i = 0; i < 8; i++) { vv[i] = S[U_OFF + tid * U_STRIDE + i]; sq += vv[i] * vv[i]; }
        float sc = sq / ((1.f + sq) * (sqrtf(sq) + 1e-8f));
        #pragma unroll
        for (int i = 0; i < 8; i++) S[U_OFF + tid * U_STRIDE + i] = vv[i] * sc;
    }
    __syncthreads();

    // ---- phase 3: u_hat from fp16 W (overlays X/WCH) ----
    for (int p = tid; p < PAIRS; p += 512) {
        int c = p % NCAPS;
        float u8[8];
        #pragma unroll
        for (int i = 0; i < 8; i++) u8[i] = S[U_OFF + c * U_STRIDE + i];
        const uint4* wp = (const uint4*)(g_Wh + (size_t)p * 128);
        #pragma unroll 4
        for (int d = 0; d < DIMD; d++) {
            uint4 r = __ldg(wp + d);
            float2 f0 = __half22float2(*(__half2*)&r.x);
            float2 f1 = __half22float2(*(__half2*)&r.y);
            float2 f2 = __half22float2(*(__half2*)&r.z);
            float2 f3 = __half22float2(*(__half2*)&r.w);
            float s = f0.x * u8[0] + f0.y * u8[1] + f1.x * u8[2] + f1.y * u8[3]
                    + f2.x * u8[4] + f2.y * u8[5] + f3.x * u8[6] + f3.y * u8[7];
            S[UHAT_OFF + p * UH_STRIDE + d] = s;
        }
    }
    __syncthreads();

    // ---- phase 4: dynamic routing ----
    for (int it = 0; it < 3; it++) {
        if (tid < NCAPS) {
            float bv[NO], m = -1e30f;
            #pragma unroll
            for (int o = 0; o < NO; o++) { bv[o] = S[BB_OFF + o * NCAPS + tid]; m = fmaxf(m, bv[o]); }
            float sum = 0.f;
            #pragma unroll
            for (int o = 0; o < NO; o++) { bv[o] = expf(bv[o] - m); sum += bv[o]; }
            float inv = 1.f / sum;
            #pragma unroll
            for (int o = 0; o < NO; o++) S[CC_OFF + o * NCAPS + tid] = bv[o] * inv;
        }
        __syncthreads();
        for (int comb = warp; comb < NO * DIMD; comb += 16) {
            int o = comb >> 4, d = comb & 15;
            float a = 0.f;
            #pragma unroll 4
            for (int c = lane; c < NCAPS; c += 32)
                a += S[CC_OFF + o * NCAPS + c] * S[UHAT_OFF + (o * NCAPS + c) * UH_STRIDE + d];
            #pragma unroll
            for (int off = 16; off; off >>= 1) a += __shfl_xor_sync(0xffffffffu, a, off);
            if (lane == 0) S[S_OFF + comb] = a;
        }
        __syncthreads();
        if (tid < NO) {
            float sq = 0.f;
            #pragma unroll
            for (int d = 0; d < DIMD; d++) { float t = S[S_OFF + tid * DIMD + d]; sq += t * t; }
            S[SC_OFF + tid] = sq / ((1.f + sq) * (sqrtf(sq) + 1e-8f));
        }
        __syncthreads();
        if (it == 2) break;
        if (tid < NO * DIMD) S[V_OFF + tid] = S[S_OFF + tid] * S[SC_OFF + (tid >> 4)];
        __syncthreads();
        for (int p = tid; p < PAIRS; p += 512) {
            int o = p / NCAPS;
            float a = 0.f;
            #pragma unroll
            for (int d = 0; d < DIMD; d++)
                a += S[UHAT_OFF + p * UH_STRIDE + d] * S[V_OFF + o * DIMD + d];
            S[BB_OFF + p] += a;
        }
        __syncthreads();
    }
    if (tid < NO * DIMD)
        out[(size_t)b * (NO * DIMD) + tid] = S[S_OFF + tid] * S[SC_OFF + (tid >> 4)];
}

// ---------------- launch ----------------
extern "C" void kernel_launch(void* const* d_in, const int* in_sizes, int n_in,
                              void* d_out, int out_size) {
    const float* x       = (const float*)d_in[0];
    const float* conv1_w = (const float*)d_in[1];
    const float* conv1_b = (const float*)d_in[2];
    const float* pconv_w = (const float*)d_in[3];
    const float* pconv_b = (const float*)d_in[4];
    const float* W       = (const float*)d_in[5];
    float* out = (float*)d_out;

    cudaFuncSetAttribute(caps_main, cudaFuncAttributeMaxDynamicSharedMemorySize, SMEM_BYTES);

    reorder_weights<<<(NO * NCAPS * DIMD * 8 + 255) / 256, 256>>>(conv1_w, pconv_w, W);
    caps_main<<<BATCH, 512, SMEM_BYTES>>>(x, conv1_b, pconv_b, out);
}

// round 5
// speedup vs baseline: 2.2632x; 1.1025x over previous
#include <cuda_runtime.h>
#include <cuda_bf16.h>
#include <cuda_fp16.h>
#include <cstdint>

// ---------------- problem constants ----------------
#define BATCH   4096
#define LSEQ    50
#define CIN     128
#define CO1     50
#define K1      9
#define LO1     42
#define KKTOT   1152
#define KCH     64      // conv1 weight chunk rows (18 chunks)
#define NCH     18
#define WPADN   72
#define CH2     64
#define CI2     42
#define K2      3
#define LO2     48
#define PK      144     // pconv padded K
#define NCAPS   384
#define NO      5
#define DIMD    16
#define PAIRS   1920

// ---------------- smem layout ----------------
// overlay region floats [0, 17280):
//   phase1: X [0,7392) 56x132 ; WB0 [7392,12000) ; WB1 [12000,16608)
//   phase2: PW2 [0,10368) 144x72
//   phase3+: UHAT as __half[34560] = 1920 x 18 (stride 18 halves)
#define X_OFF     0
#define X_STRIDE  132
#define WB0_OFF   7392
#define WB1_OFF   12000
#define PW2_OFF   0
#define UH_STRIDE 18            // halves
#define HP_OFF    17280         // 50 x 49
#define HP_STRIDE 49
#define U_OFF     19730         // 384 x 9
#define U_STRIDE  9
#define BB_OFF    23186         // 1920
#define CC_OFF    25106         // 1920
#define S_OFF     27026         // 80
#define SC_OFF    27106         // 8
#define V_OFF     27114         // 80
#define SMEM_FLOATS 27200
#define SMEM_BYTES  (SMEM_FLOATS * 4)

// device-global scratch
__device__ float  g_wtf[KKTOT * WPADN];        // conv1 w [k][co pad72] tf32
__device__ float  g_pw2[PK * WPADN];           // pconv w [kb*48+ci][ch pad72]
__device__ __half g_Wh[NO * NCAPS * DIMD * 8]; // W fp16

__device__ __forceinline__ float to_tf32(float x) {
    unsigned int u;
    asm("cvt.rna.tf32.f32 %0, %1;" : "=r"(u) : "f"(x));
    return __uint_as_float(u);
}

__device__ __forceinline__ void mma_tf32(float c[4], unsigned int a0, unsigned int a1,
                                         unsigned int a2, unsigned int a3,
                                         unsigned int b0, unsigned int b1) {
    asm volatile(
        "mma.sync.aligned.m16n8k8.row.col.f32.tf32.tf32.f32 "
        "{%0,%1,%2,%3}, {%4,%5,%6,%7}, {%8,%9}, {%0,%1,%2,%3};"
        : "+f"(c[0]), "+f"(c[1]), "+f"(c[2]), "+f"(c[3])
        : "r"(a0), "r"(a1), "r"(a2), "r"(a3), "r"(b0), "r"(b1));
}

__device__ __forceinline__ void cp16(unsigned int smem_addr, const void* gptr) {
    asm volatile("cp.async.cg.shared.global [%0], [%1], 16;"
                 :: "r"(smem_addr), "l"(gptr));
}
#define CP_COMMIT() asm volatile("cp.async.commit_group;")
#define CP_WAIT(n)  asm volatile("cp.async.wait_group %0;" :: "n"(n))

// ---------------- prologue: weight reorder / convert ----------------
__global__ void reorder_weights(const float* __restrict__ w1,
                                const float* __restrict__ w2,
                                const float* __restrict__ W) {
    int i = blockIdx.x * 256 + threadIdx.x;
    if (i < KKTOT * WPADN) {
        int k = i / WPADN, n = i % WPADN;
        float v = 0.f;
        if (n < CO1) {
            int kh = k >> 7, ci = k & 127;
            v = to_tf32(w1[n * KKTOT + ci * K1 + kh]);
        }
        g_wtf[i] = v;
    }
    if (i < PK * WPADN) {
        int kk = i / WPADN, ch = i % WPADN;
        int kb = kk / 48, ci = kk % 48;
        float v = 0.f;
        if (ch < CH2 && ci < CI2)
            v = to_tf32(w2[ch * (CI2 * K2) + ci * K2 + kb]);
        g_pw2[i] = v;
    }
    if (i < NO * NCAPS * DIMD * 8)
        g_Wh[i] = __float2half(W[i]);
}

// ---------------- fused main kernel: 1 block = 1 sample, 2 blocks/SM ----------------
__global__ __launch_bounds__(512, 2)
void caps_main(const float* __restrict__ x,
               const float* __restrict__ c1b,
               const float* __restrict__ p2b,
               float* __restrict__ out) {
    extern __shared__ float S[];
    __half* Sh = (__half*)S;
    const int b    = blockIdx.x;
    const int tid  = threadIdx.x;
    const int lane = tid & 31;
    const int warp = tid >> 5;
    const unsigned int smem_u32 = (unsigned int)__cvta_generic_to_shared(S);

    // ---- phase 0: kick off weight chunk 0 via cp.async, stage x, zero scratch ----
    {   // chunk 0 -> WB0
        const float4* src = (const float4*)g_wtf;
        #pragma unroll
        for (int j = 0; j < 3; j++) {
            int i = tid + j * 512;
            if (i < (KCH * WPADN) / 4)
                cp16(smem_u32 + (WB0_OFF + i * 4) * 4, src + i);
        }
        CP_COMMIT();
    }
    const float4* xb = (const float4*)(x + (size_t)b * (LSEQ * CIN));
    for (int i = tid; i < (LSEQ * CIN) / 4; i += 512) {
        float4 v = __ldg(xb + i);
        v.x = to_tf32(v.x); v.y = to_tf32(v.y);
        v.z = to_tf32(v.z); v.w = to_tf32(v.w);
        int l = i >> 5, c4 = i & 31;
        *(float4*)&S[X_OFF + l * X_STRIDE + c4 * 4] = v;
    }
    for (int i = tid; i < 6 * X_STRIDE; i += 512)
        S[X_OFF + 50 * X_STRIDE + i] = 0.f;
    for (int i = tid; i < CO1 * HP_STRIDE; i += 512) S[HP_OFF + i] = 0.f;
    for (int i = tid; i < PAIRS; i += 512) S[BB_OFF + i] = 0.f;

    // ---- phase 1: conv1 tf32 mma: C[l(48), co(64)], K=1152, 18 chunks dbl-buffered ----
    const int mt  = warp >> 2;        // 0..2
    const int ntg = warp & 3;         // 0..3
    const int gID = lane >> 2;        // 0..7
    const int tig = lane & 3;         // 0..3
    float acc0[4] = {0, 0, 0, 0};
    float acc1[4] = {0, 0, 0, 0};

    for (int ch = 0; ch < NCH; ch++) {
        __syncthreads();   // prev buf free for all warps; also orders staging stores
        if (ch + 1 < NCH) {
            const float4* src = (const float4*)g_wtf + (ch + 1) * ((KCH * WPADN) / 4);
            int wb = (ch + 1) & 1 ? WB1_OFF : WB0_OFF;
            #pragma unroll
            for (int j = 0; j < 3; j++) {
                int i = tid + j * 512;
                if (i < (KCH * WPADN) / 4)
                    cp16(smem_u32 + (wb + i * 4) * 4, src + i);
            }
            CP_COMMIT();
            CP_WAIT(1);    // chunk ch landed
        } else {
            CP_WAIT(0);
        }
        __syncthreads();   // chunk ch visible to all warps
        if (warp < 12) {
            const int wbuf = (ch & 1) ? WB1_OFF : WB0_OFF;
            #pragma unroll
            for (int ks = 0; ks < KCH / 8; ks++) {
                int k_lin = ch * KCH + ks * 8;
                int kh = k_lin >> 7, cb = k_lin & 127;
                int xbase = X_OFF + (mt * 16 + gID + kh) * X_STRIDE + cb + tig;
                unsigned int a0 = __float_as_uint(S[xbase]);
                unsigned int a1 = __float_as_uint(S[xbase + 8 * X_STRIDE]);
                unsigned int a2 = __float_as_uint(S[xbase + 4]);
                unsigned int a3 = __float_as_uint(S[xbase + 8 * X_STRIDE + 4]);
                int wb = wbuf + (ks * 8 + tig) * WPADN + ntg * 16 + gID;
                unsigned int b0a = __float_as_uint(S[wb]);
                unsigned int b1a = __float_as_uint(S[wb + 4 * WPADN]);
                unsigned int b0b = __float_as_uint(S[wb + 8]);
                unsigned int b1b = __float_as_uint(S[wb + 4 * WPADN + 8]);
                mma_tf32(acc0, a0, a1, a2, a3, b0a, b1a);
                mma_tf32(acc1, a0, a1, a2, a3, b0b, b1b);
            }
        }
    }
    __syncthreads();
    // epilogue: bias + relu -> Hp[co][l]
    if (warp < 12) {
        int m_lo = mt * 16 + gID, m_hi = m_lo + 8;
        #pragma unroll
        for (int t = 0; t < 2; t++) {
            float* a = (t == 0) ? acc0 : acc1;
            int n0 = ntg * 16 + t * 8 + 2 * tig;
            if (n0 < CO1) {
                float bias = __ldg(&c1b[n0]);
                if (m_lo < LO1) S[HP_OFF + n0 * HP_STRIDE + m_lo] = fmaxf(a[0] + bias, 0.f);
                if (m_hi < LO1) S[HP_OFF + n0 * HP_STRIDE + m_hi] = fmaxf(a[2] + bias, 0.f);
            }
            int n1 = n0 + 1;
            if (n1 < CO1) {
                float bias = __ldg(&c1b[n1]);
                if (m_lo < LO1) S[HP_OFF + n1 * HP_STRIDE + m_lo] = fmaxf(a[1] + bias, 0.f);
                if (m_hi < LO1) S[HP_OFF + n1 * HP_STRIDE + m_hi] = fmaxf(a[3] + bias, 0.f);
            }
        }
    }
    __syncthreads();

    // ---- phase 2: pconv tf32 mma: C[pos(48), ch(64)], K=144 (PW2 overlays X) ----
    for (int i = tid; i < (PK * WPADN) / 4; i += 512) {
        float4 v = __ldg((const float4*)g_pw2 + i);
        *(float4*)&S[PW2_OFF + i * 4] = v;
    }
    __syncthreads();
    {
        float pacc0[4] = {0, 0, 0, 0};
        float pacc1[4] = {0, 0, 0, 0};
        if (warp < 12) {
            #pragma unroll
            for (int ks = 0; ks < PK / 8; ks++) {
                int k_lin = ks * 8;
                int kb = k_lin / 48, cb = k_lin % 48;
                int abase = HP_OFF + (mt * 16 + gID + kb) * HP_STRIDE + cb + tig;
                unsigned int a0 = __float_as_uint(S[abase]);
                unsigned int a1 = __float_as_uint(S[abase + 8 * HP_STRIDE]);
                unsigned int a2 = __float_as_uint(S[abase + 4]);
                unsigned int a3 = __float_as_uint(S[abase + 8 * HP_STRIDE + 4]);
                int wb = PW2_OFF + (ks * 8 + tig) * WPADN + ntg * 16 + gID;
                unsigned int b0a = __float_as_uint(S[wb]);
                unsigned int b1a = __float_as_uint(S[wb + 4 * WPADN]);
                unsigned int b0b = __float_as_uint(S[wb + 8]);
                unsigned int b1b = __float_as_uint(S[wb + 4 * WPADN + 8]);
                mma_tf32(pacc0, a0, a1, a2, a3, b0a, b1a);
                mma_tf32(pacc1, a0, a1, a2, a3, b0b, b1b);
            }
            int m_lo = mt * 16 + gID, m_hi = m_lo + 8;
            #pragma unroll
            for (int t = 0; t < 2; t++) {
                float* a = (t == 0) ? pacc0 : pacc1;
                #pragma unroll
                for (int q = 0; q < 2; q++) {
                    int n = ntg * 16 + t * 8 + 2 * tig + q;
                    float bias = __ldg(&p2b[n]);
                    int lin0 = n * LO2 + m_lo;
                    int lin1 = n * LO2 + m_hi;
                    S[U_OFF + (lin0 >> 3) * U_STRIDE + (lin0 & 7)] = a[q] + bias;
                    S[U_OFF + (lin1 >> 3) * U_STRIDE + (lin1 & 7)] = a[q + 2] + bias;
                }
            }
        }
    }
    __syncthreads();
    if (tid < NCAPS) {
        float vv[8], sq = 0.f;
        #pragma unroll
        for (int i = 0; i < 8; i++) { vv[i] = S[U_OFF + tid * U_STRIDE + i]; sq += vv[i] * vv[i]; }
        float sc = sq / ((1.f + sq) * (sqrtf(sq) + 1e-8f));
        #pragma unroll
        for (int i = 0; i < 8; i++) S[U_OFF + tid * U_STRIDE + i] = vv[i] * sc;
    }
    __syncthreads();

    // ---- phase 3: u_hat (fp16 W -> fp16 uhat in smem; overlays X/PW2) ----
    for (int p = tid; p < PAIRS; p += 512) {
        int c = p % NCAPS;
        float u8[8];
        #pragma unroll
        for (int i = 0; i < 8; i++) u8[i] = S[U_OFF + c * U_STRIDE + i];
        const uint4* wp = (const uint4*)(g_Wh + (size_t)p * 128);
        #pragma unroll 4
        for (int d2 = 0; d2 < 8; d2++) {
            uint4 r0 = __ldg(wp + 2 * d2);
            uint4 r1 = __ldg(wp + 2 * d2 + 1);
            float2 f0 = __half22float2(*(__half2*)&r0.x);
            float2 f1 = __half22float2(*(__half2*)&r0.y);
            float2 f2 = __half22float2(*(__half2*)&r0.z);
            float2 f3 = __half22float2(*(__half2*)&r0.w);
            float s0 = f0.x * u8[0] + f0.y * u8[1] + f1.x * u8[2] + f1.y * u8[3]
                     + f2.x * u8[4] + f2.y * u8[5] + f3.x * u8[6] + f3.y * u8[7];
            f0 = __half22float2(*(__half2*)&r1.x);
            f1 = __half22float2(*(__half2*)&r1.y);
            f2 = __half22float2(*(__half2*)&r1.z);
            f3 = __half22float2(*(__half2*)&r1.w);
            float s1 = f0.x * u8[0] + f0.y * u8[1] + f1.x * u8[2] + f1.y * u8[3]
                     + f2.x * u8[4] + f2.y * u8[5] + f3.x * u8[6] + f3.y * u8[7];
            *(__half2*)&Sh[p * UH_STRIDE + 2 * d2] = __floats2half2_rn(s0, s1);
        }
    }
    __syncthreads();

    // ---- phase 4: dynamic routing ----
    for (int it = 0; it < 3; it++) {
        if (tid < NCAPS) {
            float bv[NO], m = -1e30f;
            #pragma unroll
            for (int o = 0; o < NO; o++) { bv[o] = S[BB_OFF + o * NCAPS + tid]; m = fmaxf(m, bv[o]); }
            float sum = 0.f;
            #pragma unroll
            for (int o = 0; o < NO; o++) { bv[o] = expf(bv[o] - m); sum += bv[o]; }
            float inv = 1.f / sum;
            #pragma unroll
            for (int o = 0; o < NO; o++) S[CC_OFF + o * NCAPS + tid] = bv[o] * inv;
        }
        __syncthreads();
        for (int comb = warp; comb < NO * DIMD; comb += 16) {
            int o = comb >> 4, d = comb & 15;
            float a = 0.f;
            #pragma unroll 4
            for (int c = lane; c < NCAPS; c += 32)
                a += S[CC_OFF + o * NCAPS + c]
                   * __half2float(Sh[(o * NCAPS + c) * UH_STRIDE + d]);
            #pragma unroll
            for (int off = 16; off; off >>= 1) a += __shfl_xor_sync(0xffffffffu, a, off);
            if (lane == 0) S[S_OFF + comb] = a;
        }
        __syncthreads();
        if (tid < NO) {
            float sq = 0.f;
            #pragma unroll
            for (int d = 0; d < DIMD; d++) { float t = S[S_OFF + tid * DIMD + d]; sq += t * t; }
            S[SC_OFF + tid] = sq / ((1.f + sq) * (sqrtf(sq) + 1e-8f));
        }
        __syncthreads();
        if (it == 2) break;
        if (tid < NO * DIMD) S[V_OFF + tid] = S[S_OFF + tid] * S[SC_OFF + (tid >> 4)];
        __syncthreads();
        for (int p = tid; p < PAIRS; p += 512) {
            int o = p / NCAPS;
            float a = 0.f;
            #pragma unroll
            for (int j = 0; j < 8; j++) {
                float2 f = __half22float2(*(__half2*)&Sh[p * UH_STRIDE + 2 * j]);
                a += f.x * S[V_OFF + o * DIMD + 2 * j] + f.y * S[V_OFF + o * DIMD + 2 * j + 1];
            }
            S[BB_OFF + p] += a;
        }
        __syncthreads();
    }
    if (tid < NO * DIMD)
        out[(size_t)b * (NO * DIMD) + tid] = S[S_OFF + tid] * S[SC_OFF + (tid >> 4)];
}

// ---------------- launch ----------------
extern "C" void kernel_launch(void* const* d_in, const int* in_sizes, int n_in,
                              void* d_out, int out_size) {
    const float* x       = (const float*)d_in[0];
    const float* conv1_w = (const float*)d_in[1];
    const float* conv1_b = (const float*)d_in[2];
    const float* pconv_w = (const float*)d_in[3];
    const float* pconv_b = (const float*)d_in[4];
    const float* W       = (const float*)d_in[5];
    float* out = (float*)d_out;

    cudaFuncSetAttribute(caps_main, cudaFuncAttributeMaxDynamicSharedMemorySize, SMEM_BYTES);

    reorder_weights<<<(NO * NCAPS * DIMD * 8 + 255) / 256, 256>>>(conv1_w, pconv_w, W);
    caps_main<<<BATCH, 512, SMEM_BYTES>>>(x, conv1_b, pconv_b, out);
}

// round 8
// speedup vs baseline: 2.7475x; 1.2140x over previous
#include <cuda_runtime.h>
#include <cuda_bf16.h>
#include <cuda_fp16.h>
#include <cstdint>

// ---------------- problem constants ----------------
#define BATCH   4096
#define LSEQ    50
#define CIN     128
#define CO1     50
#define K1      9
#define LO1     42
#define KKTOT   1152
#define KCH     64      // conv1 k-chunk (18 chunks)
#define NCH     18
#define CH2     64
#define CI2     42
#define K2      3
#define LO2     48
#define PK      144     // pconv padded K (3*48)
#define NCAPS   384
#define NO      5
#define DIMD    16
#define PAIRS   1920

// ---------------- smem layout ----------------
// Byte overlay region [0, 69120):
//   phase1: Xh halves [0,15232) 56x136h ; WB0 [15232,24448) 64x72h ; WB1 [24448,33664)
//   phase2: PWH halves [0,18432) 64x144h
//   phase3+: UHAT halves [0,69120) 1920x18h
// half indices:
#define XH_OFF    0
#define XH_STR    136
#define WB0H      7616
#define WB1H      12224
#define WBSTR     72
#define PWH_OFF   0
#define PWSTR     144
#define UH_STRIDE 18
#define HPH_OFF   34560        // halves; 50 x 56
#define HPH_STR   56
// float indices:
#define U_OFF     18680        // 384 x 9
#define U_STRIDE  9
#define BB_OFF    22136
#define CC_OFF    24056
#define S_OFF     25976
#define SC_OFF    26056
#define V_OFF     26064
#define SMEM_FLOATS 26144
#define SMEM_BYTES  (SMEM_FLOATS * 4)

// device-global scratch
__device__ __half g_w16[NCH * 64 * WBSTR];     // conv1 w fp16: [chunk][co 64][72h]
__device__ __half g_pw16[CH2 * PWSTR];         // pconv w fp16: [ch][144h] (k-contig)
__device__ __half g_Wh[NO * NCAPS * DIMD * 8]; // routing W fp16

__device__ __forceinline__ void mma_f16(float c[4], unsigned a0, unsigned a1,
                                        unsigned a2, unsigned a3,
                                        unsigned b0, unsigned b1) {
    asm volatile(
        "mma.sync.aligned.m16n8k16.row.col.f32.f16.f16.f32 "
        "{%0,%1,%2,%3}, {%4,%5,%6,%7}, {%8,%9}, {%0,%1,%2,%3};"
        : "+f"(c[0]), "+f"(c[1]), "+f"(c[2]), "+f"(c[3])
        : "r"(a0), "r"(a1), "r"(a2), "r"(a3), "r"(b0), "r"(b1));
}

__device__ __forceinline__ void cp16(unsigned smem_addr, const void* gptr) {
    asm volatile("cp.async.cg.shared.global [%0], [%1], 16;"
                 :: "r"(smem_addr), "l"(gptr));
}
#define CP_COMMIT() asm volatile("cp.async.commit_group;")
#define CP_WAIT(n)  asm volatile("cp.async.wait_group %0;" :: "n"(n))

// ---------------- prologue: weight reorder / convert ----------------
__global__ void reorder_weights(const float* __restrict__ w1,
                                const float* __restrict__ w2,
                                const float* __restrict__ W) {
    int i = blockIdx.x * 256 + threadIdx.x;
    if (i < NCH * 64 * WBSTR) {
        int ch = i / (64 * WBSTR);
        int r  = i % (64 * WBSTR);
        int co = r / WBSTR, j = r % WBSTR;
        float v = 0.f;
        if (j < KCH && co < CO1) {
            int k = ch * KCH + j;
            int kh = k >> 7, ci = k & 127;
            v = w1[co * KKTOT + ci * K1 + kh];
        }
        g_w16[i] = __float2half(v);
    }
    if (i < CH2 * PWSTR) {
        int chn = i / PWSTR, kk = i % PWSTR;
        int kb = kk / 48, ci = kk % 48;
        float v = 0.f;
        if (ci < CI2)
            v = w2[chn * (CI2 * K2) + ci * K2 + kb];
        g_pw16[i] = __float2half(v);
    }
    if (i < NO * NCAPS * DIMD * 8)
        g_Wh[i] = __float2half(W[i]);
}

// ---------------- fused main kernel: 1 block = 1 sample, 2 blocks/SM ----------------
__global__ __launch_bounds__(512, 2)
void caps_main(const float* __restrict__ x,
               const float* __restrict__ c1b,
               const float* __restrict__ p2b,
               float* __restrict__ out) {
    extern __shared__ float S[];
    __half* Sh = (__half*)S;
    const int b    = blockIdx.x;
    const int tid  = threadIdx.x;
    const int lane = tid & 31;
    const int warp = tid >> 5;
    const unsigned smem_u32 = (unsigned)__cvta_generic_to_shared(S);

    // ---- phase 0: cp.async chunk 0, stage x->fp16, zero scratch ----
    {
        const uint4* src = (const uint4*)g_w16;   // chunk = 576 x 16B
        #pragma unroll
        for (int j = 0; j < 2; j++) {
            int i = tid + j * 512;
            if (i < 576) cp16(smem_u32 + WB0H * 2 + i * 16, src + i);
        }
        CP_COMMIT();
    }
    const float4* xb = (const float4*)(x + (size_t)b * (LSEQ * CIN));
    for (int i = tid; i < (LSEQ * CIN) / 4; i += 512) {
        float4 v = __ldg(xb + i);
        __half2 h0 = __floats2half2_rn(v.x, v.y);
        __half2 h1 = __floats2half2_rn(v.z, v.w);
        int l = i >> 5, c4 = i & 31;
        uint2 pk;
        pk.x = *(unsigned*)&h0; pk.y = *(unsigned*)&h1;
        *(uint2*)&Sh[XH_OFF + l * XH_STR + c4 * 4] = pk;
    }
    // zero x rows 50..55 (read via padded M tiles) : 816 halves = 408 words
    for (int i = tid; i < (6 * XH_STR) / 2; i += 512)
        *(unsigned*)&Sh[XH_OFF + 50 * XH_STR + i * 2] = 0u;
    // zero Hp (50x56 halves = 1400 words)
    for (int i = tid; i < (CO1 * HPH_STR) / 2; i += 512)
        *(unsigned*)&Sh[HPH_OFF + i * 2] = 0u;
    for (int i = tid; i < PAIRS; i += 512) S[BB_OFF + i] = 0.f;

    // ---- phase 1: conv1 fp16 mma: C[l(48), co(64)], K=1152, 18 chunks dbl-buffered ----
    const int mt  = warp >> 2;        // 0..2
    const int ntg = warp & 3;         // 0..3
    const int gID = lane >> 2;        // 0..7
    const int tig = lane & 3;         // 0..3
    float acc0[4] = {0, 0, 0, 0};
    float acc1[4] = {0, 0, 0, 0};

    for (int ch = 0; ch < NCH; ch++) {
        __syncthreads();   // prev buf free; orders staging
        if (ch + 1 < NCH) {
            const uint4* src = (const uint4*)g_w16 + (ch + 1) * 576;
            int wbh = ((ch + 1) & 1) ? WB1H : WB0H;
            #pragma unroll
            for (int j = 0; j < 2; j++) {
                int i = tid + j * 512;
                if (i < 576) cp16(smem_u32 + wbh * 2 + i * 16, src + i);
            }
            CP_COMMIT();
            CP_WAIT(1);
        } else {
            CP_WAIT(0);
        }
        __syncthreads();
        if (warp < 12) {
            const int wbh = (ch & 1) ? WB1H : WB0H;
            #pragma unroll
            for (int ks = 0; ks < KCH / 16; ks++) {
                int k_lin = ch * KCH + ks * 16;
                int kh = k_lin >> 7, cb = k_lin & 127;
                int abase = XH_OFF + (mt * 16 + gID + kh) * XH_STR + cb + 2 * tig;
                unsigned a0 = *(unsigned*)&Sh[abase];
                unsigned a1 = *(unsigned*)&Sh[abase + 8 * XH_STR];
                unsigned a2 = *(unsigned*)&Sh[abase + 8];
                unsigned a3 = *(unsigned*)&Sh[abase + 8 * XH_STR + 8];
                int bbase = wbh + (ntg * 16 + gID) * WBSTR + ks * 16 + 2 * tig;
                unsigned b0a = *(unsigned*)&Sh[bbase];
                unsigned b1a = *(unsigned*)&Sh[bbase + 8];
                unsigned b0b = *(unsigned*)&Sh[bbase + 8 * WBSTR];
                unsigned b1b = *(unsigned*)&Sh[bbase + 8 * WBSTR + 8];
                mma_f16(acc0, a0, a1, a2, a3, b0a, b1a);
                mma_f16(acc1, a0, a1, a2, a3, b0b, b1b);
            }
        }
    }
    __syncthreads();
    // epilogue: bias + relu -> HpH[co][l] (fp16)
    if (warp < 12) {
        int m_lo = mt * 16 + gID, m_hi = m_lo + 8;
        #pragma unroll
        for (int t = 0; t < 2; t++) {
            float* a = (t == 0) ? acc0 : acc1;
            #pragma unroll
            for (int q = 0; q < 2; q++) {
                int n = ntg * 16 + t * 8 + 2 * tig + q;
                if (n < CO1) {
                    float bias = __ldg(&c1b[n]);
                    if (m_lo < LO1)
                        Sh[HPH_OFF + n * HPH_STR + m_lo] = __float2half(fmaxf(a[q] + bias, 0.f));
                    if (m_hi < LO1)
                        Sh[HPH_OFF + n * HPH_STR + m_hi] = __float2half(fmaxf(a[q + 2] + bias, 0.f));
                }
            }
        }
    }
    __syncthreads();

    // ---- phase 2: pconv fp16 mma: C[pos(48), ch(64)], K=144 (PWH overlays X) ----
    for (int i = tid; i < (CH2 * PWSTR) / 8; i += 512) {
        uint4 v = __ldg((const uint4*)g_pw16 + i);
        *(uint4*)&Sh[PWH_OFF + i * 8] = v;
    }
    __syncthreads();
    {
        float pacc0[4] = {0, 0, 0, 0};
        float pacc1[4] = {0, 0, 0, 0};
        if (warp < 12) {
            #pragma unroll
            for (int ks = 0; ks < PK / 16; ks++) {
                int k_lin = ks * 16;
                int kb = k_lin / 48, cb = k_lin % 48;
                int abase = HPH_OFF + (mt * 16 + gID + kb) * HPH_STR + cb + 2 * tig;
                unsigned a0 = *(unsigned*)&Sh[abase];
                unsigned a1 = *(unsigned*)&Sh[abase + 8 * HPH_STR];
                unsigned a2 = *(unsigned*)&Sh[abase + 8];
                unsigned a3 = *(unsigned*)&Sh[abase + 8 * HPH_STR + 8];
                int bbase = PWH_OFF + (ntg * 16 + gID) * PWSTR + ks * 16 + 2 * tig;
                unsigned b0a = *(unsigned*)&Sh[bbase];
                unsigned b1a = *(unsigned*)&Sh[bbase + 8];
                unsigned b0b = *(unsigned*)&Sh[bbase + 8 * PWSTR];
                unsigned b1b = *(unsigned*)&Sh[bbase + 8 * PWSTR + 8];
                mma_f16(pacc0, a0, a1, a2, a3, b0a, b1a);
                mma_f16(pacc1, a0, a1, a2, a3, b0b, b1b);
            }
            int m_lo = mt * 16 + gID, m_hi = m_lo + 8;
            #pragma unroll
            for (int t = 0; t < 2; t++) {
                float* a = (t == 0) ? pacc0 : pacc1;
                #pragma unroll
                for (int q = 0; q < 2; q++) {
                    int n = ntg * 16 + t * 8 + 2 * tig + q;
                    float bias = __ldg(&p2b[n]);
                    int lin0 = n * LO2 + m_lo;
                    int lin1 = n * LO2 + m_hi;
                    S[U_OFF + (lin0 >> 3) * U_STRIDE + (lin0 & 7)] = a[q] + bias;
                    S[U_OFF + (lin1 >> 3) * U_STRIDE + (lin1 & 7)] = a[q + 2] + bias;
                }
            }
        }
    }
    __syncthreads();
    if (tid < NCAPS) {
        float vv[8], sq = 0.f;
        #pragma unroll
        for (int i = 0; i < 8; i++) { vv[i] = S[U_OFF + tid * U_STRIDE + i]; sq += vv[i] * vv[i]; }
        float sc = sq / ((1.f + sq) * (sqrtf(sq) + 1e-8f));
        #pragma unroll
        for (int i = 0; i < 8; i++) S[U_OFF + tid * U_STRIDE + i] = vv[i] * sc;
    }
    __syncthreads();

    // ---- phase 3: u_hat (fp16 W LDG -> fp16 uhat smem; overlays X/PWH) ----
    for (int p = tid; p < PAIRS; p += 512) {
        int c = p % NCAPS;
        float u8[8];
        #pragma unroll
        for (int i = 0; i < 8; i++) u8[i] = S[U_OFF + c * U_STRIDE + i];
        const uint4* wp = (const uint4*)(g_Wh + (size_t)p * 128);
        #pragma unroll 4
        for (int d2 = 0; d2 < 8; d2++) {
            uint4 r0 = __ldg(wp + 2 * d2);
            uint4 r1 = __ldg(wp + 2 * d2 + 1);
            float2 f0 = __half22float2(*(__half2*)&r0.x);
            float2 f1 = __half22float2(*(__half2*)&r0.y);
            float2 f2 = __half22float2(*(__half2*)&r0.z);
            float2 f3 = __half22float2(*(__half2*)&r0.w);
            float s0 = f0.x * u8[0] + f0.y * u8[1] + f1.x * u8[2] + f1.y * u8[3]
                     + f2.x * u8[4] + f2.y * u8[5] + f3.x * u8[6] + f3.y * u8[7];
            f0 = __half22float2(*(__half2*)&r1.x);
            f1 = __half22float2(*(__half2*)&r1.y);
            f2 = __half22float2(*(__half2*)&r1.z);
            f3 = __half22float2(*(__half2*)&r1.w);
            float s1 = f0.x * u8[0] + f0.y * u8[1] + f1.x * u8[2] + f1.y * u8[3]
                     + f2.x * u8[4] + f2.y * u8[5] + f3.x * u8[6] + f3.y * u8[7];
            *(__half2*)&Sh[p * UH_STRIDE + 2 * d2] = __floats2half2_rn(s0, s1);
        }
    }
    __syncthreads();

    // ---- phase 4: dynamic routing ----
    for (int it = 0; it < 3; it++) {
        if (tid < NCAPS) {
            float bv[NO], m = -1e30f;
            #pragma unroll
            for (int o = 0; o < NO; o++) { bv[o] = S[BB_OFF + o * NCAPS + tid]; m = fmaxf(m, bv[o]); }
            float sum = 0.f;
            #pragma unroll
            for (int o = 0; o < NO; o++) { bv[o] = expf(bv[o] - m); sum += bv[o]; }
            float inv = 1.f / sum;
            #pragma unroll
            for (int o = 0; o < NO; o++) S[CC_OFF + o * NCAPS + tid] = bv[o] * inv;
        }
        __syncthreads();
        // s[o][2dp..2dp+1] via half2 uhat reads: 40 combos
        for (int comb = warp; comb < NO * 8; comb += 16) {
            int o = comb >> 3, dp = comb & 7;
            float a0 = 0.f, a1 = 0.f;
            #pragma unroll 4
            for (int c = lane; c < NCAPS; c += 32) {
                float cc = S[CC_OFF + o * NCAPS + c];
                float2 f = __half22float2(*(__half2*)&Sh[(o * NCAPS + c) * UH_STRIDE + 2 * dp]);
                a0 += cc * f.x;
                a1 += cc * f.y;
            }
            #pragma unroll
            for (int off = 16; off; off >>= 1) {
                a0 += __shfl_xor_sync(0xffffffffu, a0, off);
                a1 += __shfl_xor_sync(0xffffffffu, a1, off);
            }
            if (lane == 0) {
                S[S_OFF + o * DIMD + 2 * dp]     = a0;
                S[S_OFF + o * DIMD + 2 * dp + 1] = a1;
            }
        }
        __syncthreads();
        if (tid < NO) {
            float sq = 0.f;
            #pragma unroll
            for (int d = 0; d < DIMD; d++) { float t = S[S_OFF + tid * DIMD + d]; sq += t * t; }
            S[SC_OFF + tid] = sq / ((1.f + sq) * (sqrtf(sq) + 1e-8f));
        }
        __syncthreads();
        if (it == 2) break;
        if (tid < NO * DIMD) S[V_OFF + tid] = S[S_OFF + tid] * S[SC_OFF + (tid >> 4)];
        __syncthreads();
        for (int p = tid; p < PAIRS; p += 512) {
            int o = p / NCAPS;
            float a = 0.f;
            #pragma unroll
            for (int j = 0; j < 8; j++) {
                float2 f = __half22float2(*(__half2*)&Sh[p * UH_STRIDE + 2 * j]);
                a += f.x * S[V_OFF + o * DIMD + 2 * j] + f.y * S[V_OFF + o * DIMD + 2 * j + 1];
            }
            S[BB_OFF + p] += a;
        }
        __syncthreads();
    }
    if (tid < NO * DIMD)
        out[(size_t)b * (NO * DIMD) + tid] = S[S_OFF + tid] * S[SC_OFF + (tid >> 4)];
}

// ---------------- launch ----------------
extern "C" void kernel_launch(void* const* d_in, const int* in_sizes, int n_in,
                              void* d_out, int out_size) {
    const float* x       = (const float*)d_in[0];
    const float* conv1_w = (const float*)d_in[1];
    const float* conv1_b = (const float*)d_in[2];
    const float* pconv_w = (const float*)d_in[3];
    const float* pconv_b = (const float*)d_in[4];
    const float* W       = (const float*)d_in[5];
    float* out = (float*)d_out;

    cudaFuncSetAttribute(caps_main, cudaFuncAttributeMaxDynamicSharedMemorySize, SMEM_BYTES);

    reorder_weights<<<(NO * NCAPS * DIMD * 8 + 255) / 256, 256>>>(conv1_w, pconv_w, W);
    caps_main<<<BATCH, 512, SMEM_BYTES>>>(x, conv1_b, pconv_b, out);
}

// round 9
// speedup vs baseline: 5.0467x; 1.8368x over previous
#include <cuda_runtime.h>
#include <cuda_bf16.h>
#include <cuda_fp16.h>
#include <cstdint>

// ---------------- problem constants ----------------
#define BATCH   4096
#define LSEQ    50
#define CIN     128
#define CO1     50
#define K1      9
#define LO1     42
#define KKTOT   1152
#define KCH     64      // conv1 k-chunk (18 chunks)
#define NCH     18
#define CH2     64
#define CI2     42
#define K2      3
#define LO2     48
#define PK      144     // pconv padded K (3*48)
#define NCAPS   384
#define NO      5
#define DIMD    16
#define PAIRS   1920

// ---------------- smem layout ----------------
// Byte overlay region [0, 61440):
//   phase1: Xh halves [0,15232) 56x136h ; WB0 [15232,24448) 64x72h ; WB1 [24448,33664)
//   phase2: PWH halves [0,18432) 64x144h
//   phase3+: UH2 half2[15360] = [o(5)][dp(8)][c(384)]  (c-contiguous!)
// half indices:
#define XH_OFF    0
#define XH_STR    136
#define WB0H      7616
#define WB1H      12224
#define WBSTR     72
#define PWH_OFF   0
#define PWSTR     144
#define HPH_OFF   30720        // halves; 50 x 56 (starts at byte 61440)
#define HPH_STR   56
// float indices:
#define U_OFF     16760        // 384 x 9
#define U_STRIDE  9
#define BB_OFF    20216
#define CC_OFF    22136
#define S_OFF     24056
#define SC_OFF    24136
#define V_OFF     24144
#define SMEM_FLOATS 24224
#define SMEM_BYTES  (SMEM_FLOATS * 4)

// device-global scratch
__device__ __half g_w16[NCH * 64 * WBSTR];     // conv1 w fp16: [chunk][co 64][72h]
__device__ __half g_pw16[CH2 * PWSTR];         // pconv w fp16: [ch][144h]
__device__ __half g_Wt[PAIRS * DIMD * 8];      // routing W fp16, TRANSPOSED:
                                               // [p>>5][d][p&31][i]  (warp-coalesced)

__device__ __forceinline__ void mma_f16(float c[4], unsigned a0, unsigned a1,
                                        unsigned a2, unsigned a3,
                                        unsigned b0, unsigned b1) {
    asm volatile(
        "mma.sync.aligned.m16n8k16.row.col.f32.f16.f16.f32 "
        "{%0,%1,%2,%3}, {%4,%5,%6,%7}, {%8,%9}, {%0,%1,%2,%3};"
        : "+f"(c[0]), "+f"(c[1]), "+f"(c[2]), "+f"(c[3])
        : "r"(a0), "r"(a1), "r"(a2), "r"(a3), "r"(b0), "r"(b1));
}

__device__ __forceinline__ void cp16(unsigned smem_addr, const void* gptr) {
    asm volatile("cp.async.cg.shared.global [%0], [%1], 16;"
                 :: "r"(smem_addr), "l"(gptr));
}
#define CP_COMMIT() asm volatile("cp.async.commit_group;")
#define CP_WAIT(n)  asm volatile("cp.async.wait_group %0;" :: "n"(n))

// ---------------- prologue: weight reorder / convert ----------------
__global__ void reorder_weights(const float* __restrict__ w1,
                                const float* __restrict__ w2,
                                const float* __restrict__ W) {
    int i = blockIdx.x * 256 + threadIdx.x;
    if (i < NCH * 64 * WBSTR) {
        int ch = i / (64 * WBSTR);
        int r  = i % (64 * WBSTR);
        int co = r / WBSTR, j = r % WBSTR;
        float v = 0.f;
        if (j < KCH && co < CO1) {
            int k = ch * KCH + j;
            int kh = k >> 7, ci = k & 127;
            v = w1[co * KKTOT + ci * K1 + kh];
        }
        g_w16[i] = __float2half(v);
    }
    if (i < CH2 * PWSTR) {
        int chn = i / PWSTR, kk = i % PWSTR;
        int kb = kk / 48, ci = kk % 48;
        float v = 0.f;
        if (ci < CI2)
            v = w2[chn * (CI2 * K2) + ci * K2 + kb];
        g_pw16[i] = __float2half(v);
    }
    if (i < PAIRS * DIMD * 8) {
        // dst index i = (((pg*16 + d)*32 + ln)*8 + e); src = W[(p*16+d)*8+e], p = pg*32+ln
        int e  = i & 7;
        int t  = i >> 3;
        int ln = t & 31;
        int t2 = t >> 5;
        int d  = t2 & 15;
        int pg = t2 >> 4;
        int p  = pg * 32 + ln;
        g_Wt[i] = __float2half(W[(p * 16 + d) * 8 + e]);
    }
}

// ---------------- fused main kernel: 1 block = 1 sample, 2 blocks/SM ----------------
__global__ __launch_bounds__(512, 2)
void caps_main(const float* __restrict__ x,
               const float* __restrict__ c1b,
               const float* __restrict__ p2b,
               float* __restrict__ out) {
    extern __shared__ float S[];
    __half*  Sh  = (__half*)S;
    __half2* Sh2 = (__half2*)S;     // UH2 base (overlay offset 0)
    const int b    = blockIdx.x;
    const int tid  = threadIdx.x;
    const int lane = tid & 31;
    const int warp = tid >> 5;
    const unsigned smem_u32 = (unsigned)__cvta_generic_to_shared(S);

    // ---- phase 0: cp.async chunk 0, stage x->fp16, zero scratch ----
    {
        const uint4* src = (const uint4*)g_w16;   // chunk = 576 x 16B
        #pragma unroll
        for (int j = 0; j < 2; j++) {
            int i = tid + j * 512;
            if (i < 576) cp16(smem_u32 + WB0H * 2 + i * 16, src + i);
        }
        CP_COMMIT();
    }
    const float4* xb = (const float4*)(x + (size_t)b * (LSEQ * CIN));
    for (int i = tid; i < (LSEQ * CIN) / 4; i += 512) {
        float4 v = __ldg(xb + i);
        __half2 h0 = __floats2half2_rn(v.x, v.y);
        __half2 h1 = __floats2half2_rn(v.z, v.w);
        int l = i >> 5, c4 = i & 31;
        uint2 pk;
        pk.x = *(unsigned*)&h0; pk.y = *(unsigned*)&h1;
        *(uint2*)&Sh[XH_OFF + l * XH_STR + c4 * 4] = pk;
    }
    for (int i = tid; i < (6 * XH_STR) / 2; i += 512)
        *(unsigned*)&Sh[XH_OFF + 50 * XH_STR + i * 2] = 0u;
    for (int i = tid; i < (CO1 * HPH_STR) / 2; i += 512)
        *(unsigned*)&Sh[HPH_OFF + i * 2] = 0u;
    for (int i = tid; i < PAIRS; i += 512) S[BB_OFF + i] = 0.f;

    // ---- phase 1: conv1 fp16 mma: C[l(48), co(64)], K=1152, dbl-buffered ----
    const int mt  = warp >> 2;
    const int ntg = warp & 3;
    const int gID = lane >> 2;
    const int tig = lane & 3;
    float acc0[4] = {0, 0, 0, 0};
    float acc1[4] = {0, 0, 0, 0};

    for (int ch = 0; ch < NCH; ch++) {
        __syncthreads();
        if (ch + 1 < NCH) {
            const uint4* src = (const uint4*)g_w16 + (ch + 1) * 576;
            int wbh = ((ch + 1) & 1) ? WB1H : WB0H;
            #pragma unroll
            for (int j = 0; j < 2; j++) {
                int i = tid + j * 512;
                if (i < 576) cp16(smem_u32 + wbh * 2 + i * 16, src + i);
            }
            CP_COMMIT();
            CP_WAIT(1);
        } else {
            CP_WAIT(0);
        }
        __syncthreads();
        if (warp < 12) {
            const int wbh = (ch & 1) ? WB1H : WB0H;
            #pragma unroll
            for (int ks = 0; ks < KCH / 16; ks++) {
                int k_lin = ch * KCH + ks * 16;
                int kh = k_lin >> 7, cb = k_lin & 127;
                int abase = XH_OFF + (mt * 16 + gID + kh) * XH_STR + cb + 2 * tig;
                unsigned a0 = *(unsigned*)&Sh[abase];
                unsigned a1 = *(unsigned*)&Sh[abase + 8 * XH_STR];
                unsigned a2 = *(unsigned*)&Sh[abase + 8];
                unsigned a3 = *(unsigned*)&Sh[abase + 8 * XH_STR + 8];
                int bbase = wbh + (ntg * 16 + gID) * WBSTR + ks * 16 + 2 * tig;
                unsigned b0a = *(unsigned*)&Sh[bbase];
                unsigned b1a = *(unsigned*)&Sh[bbase + 8];
                unsigned b0b = *(unsigned*)&Sh[bbase + 8 * WBSTR];
                unsigned b1b = *(unsigned*)&Sh[bbase + 8 * WBSTR + 8];
                mma_f16(acc0, a0, a1, a2, a3, b0a, b1a);
                mma_f16(acc1, a0, a1, a2, a3, b0b, b1b);
            }
        }
    }
    __syncthreads();
    // epilogue: bias + relu -> HpH[co][l] (fp16)
    if (warp < 12) {
        int m_lo = mt * 16 + gID, m_hi = m_lo + 8;
        #pragma unroll
        for (int t = 0; t < 2; t++) {
            float* a = (t == 0) ? acc0 : acc1;
            #pragma unroll
            for (int q = 0; q < 2; q++) {
                int n = ntg * 16 + t * 8 + 2 * tig + q;
                if (n < CO1) {
                    float bias = __ldg(&c1b[n]);
                    if (m_lo < LO1)
                        Sh[HPH_OFF + n * HPH_STR + m_lo] = __float2half(fmaxf(a[q] + bias, 0.f));
                    if (m_hi < LO1)
                        Sh[HPH_OFF + n * HPH_STR + m_hi] = __float2half(fmaxf(a[q + 2] + bias, 0.f));
                }
            }
        }
    }
    __syncthreads();

    // ---- phase 2: pconv fp16 mma: C[pos(48), ch(64)], K=144 ----
    for (int i = tid; i < (CH2 * PWSTR) / 8; i += 512) {
        uint4 v = __ldg((const uint4*)g_pw16 + i);
        *(uint4*)&Sh[PWH_OFF + i * 8] = v;
    }
    __syncthreads();
    {
        float pacc0[4] = {0, 0, 0, 0};
        float pacc1[4] = {0, 0, 0, 0};
        if (warp < 12) {
            #pragma unroll
            for (int ks = 0; ks < PK / 16; ks++) {
                int k_lin = ks * 16;
                int kb = k_lin / 48, cb = k_lin % 48;
                int abase = HPH_OFF + (mt * 16 + gID + kb) * HPH_STR + cb + 2 * tig;
                unsigned a0 = *(unsigned*)&Sh[abase];
                unsigned a1 = *(unsigned*)&Sh[abase + 8 * HPH_STR];
                unsigned a2 = *(unsigned*)&Sh[abase + 8];
                unsigned a3 = *(unsigned*)&Sh[abase + 8 * HPH_STR + 8];
                int bbase = PWH_OFF + (ntg * 16 + gID) * PWSTR + ks * 16 + 2 * tig;
                unsigned b0a = *(unsigned*)&Sh[bbase];
                unsigned b1a = *(unsigned*)&Sh[bbase + 8];
                unsigned b0b = *(unsigned*)&Sh[bbase + 8 * PWSTR];
                unsigned b1b = *(unsigned*)&Sh[bbase + 8 * PWSTR + 8];
                mma_f16(pacc0, a0, a1, a2, a3, b0a, b1a);
                mma_f16(pacc1, a0, a1, a2, a3, b0b, b1b);
            }
            int m_lo = mt * 16 + gID, m_hi = m_lo + 8;
            #pragma unroll
            for (int t = 0; t < 2; t++) {
                float* a = (t == 0) ? pacc0 : pacc1;
                #pragma unroll
                for (int q = 0; q < 2; q++) {
                    int n = ntg * 16 + t * 8 + 2 * tig + q;
                    float bias = __ldg(&p2b[n]);
                    int lin0 = n * LO2 + m_lo;
                    int lin1 = n * LO2 + m_hi;
                    S[U_OFF + (lin0 >> 3) * U_STRIDE + (lin0 & 7)] = a[q] + bias;
                    S[U_OFF + (lin1 >> 3) * U_STRIDE + (lin1 & 7)] = a[q + 2] + bias;
                }
            }
        }
    }
    __syncthreads();
    if (tid < NCAPS) {
        float vv[8], sq = 0.f;
        #pragma unroll
        for (int i = 0; i < 8; i++) { vv[i] = S[U_OFF + tid * U_STRIDE + i]; sq += vv[i] * vv[i]; }
        float sc = sq / ((1.f + sq) * (sqrtf(sq) + 1e-8f));
        #pragma unroll
        for (int i = 0; i < 8; i++) S[U_OFF + tid * U_STRIDE + i] = vv[i] * sc;
    }
    __syncthreads();

    // ---- phase 3: u_hat -> UH2[o][dp][c] half2 (coalesced W loads + stores) ----
    for (int p = tid; p < PAIRS; p += 512) {
        int c = p % NCAPS;
        int o = p / NCAPS;
        float u8[8];
        #pragma unroll
        for (int i = 0; i < 8; i++) u8[i] = S[U_OFF + c * U_STRIDE + i];
        // transposed W: lane-coalesced 16B per (p, d)
        const uint4* wp = (const uint4*)g_Wt + ((p >> 5) * 16) * 32 + (p & 31);
        #pragma unroll 4
        for (int dp = 0; dp < 8; dp++) {
            uint4 r0 = __ldg(wp + (2 * dp) * 32);
            uint4 r1 = __ldg(wp + (2 * dp + 1) * 32);
            float2 f0 = __half22float2(*(__half2*)&r0.x);
            float2 f1 = __half22float2(*(__half2*)&r0.y);
            float2 f2 = __half22float2(*(__half2*)&r0.z);
            float2 f3 = __half22float2(*(__half2*)&r0.w);
            float s0 = f0.x * u8[0] + f0.y * u8[1] + f1.x * u8[2] + f1.y * u8[3]
                     + f2.x * u8[4] + f2.y * u8[5] + f3.x * u8[6] + f3.y * u8[7];
            f0 = __half22float2(*(__half2*)&r1.x);
            f1 = __half22float2(*(__half2*)&r1.y);
            f2 = __half22float2(*(__half2*)&r1.z);
            f3 = __half22float2(*(__half2*)&r1.w);
            float s1 = f0.x * u8[0] + f0.y * u8[1] + f1.x * u8[2] + f1.y * u8[3]
                     + f2.x * u8[4] + f2.y * u8[5] + f3.x * u8[6] + f3.y * u8[7];
            Sh2[(o * 8 + dp) * NCAPS + c] = __floats2half2_rn(s0, s1);
        }
    }
    __syncthreads();

    // ---- phase 4: dynamic routing (uhat reads all c-coalesced) ----
    for (int it = 0; it < 3; it++) {
        if (tid < NCAPS) {
            float bv[NO], m = -1e30f;
            #pragma unroll
            for (int o = 0; o < NO; o++) { bv[o] = S[BB_OFF + o * NCAPS + tid]; m = fmaxf(m, bv[o]); }
            float sum = 0.f;
            #pragma unroll
            for (int o = 0; o < NO; o++) { bv[o] = expf(bv[o] - m); sum += bv[o]; }
            float inv = 1.f / sum;
            #pragma unroll
            for (int o = 0; o < NO; o++) S[CC_OFF + o * NCAPS + tid] = bv[o] * inv;
        }
        __syncthreads();
        // s[o][2dp..2dp+1]: 40 combos, lanes scan c contiguously
        for (int comb = warp; comb < NO * 8; comb += 16) {
            int o = comb >> 3, dp = comb & 7;
            float a0 = 0.f, a1 = 0.f;
            #pragma unroll 4
            for (int c = lane; c < NCAPS; c += 32) {
                float cc = S[CC_OFF + o * NCAPS + c];
                float2 f = __half22float2(Sh2[(o * 8 + dp) * NCAPS + c]);
                a0 += cc * f.x;
                a1 += cc * f.y;
            }
            #pragma unroll
            for (int off = 16; off; off >>= 1) {
                a0 += __shfl_xor_sync(0xffffffffu, a0, off);
                a1 += __shfl_xor_sync(0xffffffffu, a1, off);
            }
            if (lane == 0) {
                S[S_OFF + o * DIMD + 2 * dp]     = a0;
                S[S_OFF + o * DIMD + 2 * dp + 1] = a1;
            }
        }
        __syncthreads();
        if (tid < NO) {
            float sq = 0.f;
            #pragma unroll
            for (int d = 0; d < DIMD; d++) { float t = S[S_OFF + tid * DIMD + d]; sq += t * t; }
            S[SC_OFF + tid] = sq / ((1.f + sq) * (sqrtf(sq) + 1e-8f));
        }
        __syncthreads();
        if (it == 2) break;
        if (tid < NO * DIMD) S[V_OFF + tid] = S[S_OFF + tid] * S[SC_OFF + (tid >> 4)];
        __syncthreads();
        for (int p = tid; p < PAIRS; p += 512) {
            int o = p / NCAPS;
            int c = p % NCAPS;
            float a = 0.f;
            #pragma unroll
            for (int j = 0; j < 8; j++) {
                float2 f = __half22float2(Sh2[(o * 8 + j) * NCAPS + c]);
                a += f.x * S[V_OFF + o * DIMD + 2 * j] + f.y * S[V_OFF + o * DIMD + 2 * j + 1];
            }
            S[BB_OFF + p] += a;
        }
        __syncthreads();
    }
    if (tid < NO * DIMD)
        out[(size_t)b * (NO * DIMD) + tid] = S[S_OFF + tid] * S[SC_OFF + (tid >> 4)];
}

// ---------------- launch ----------------
extern "C" void kernel_launch(void* const* d_in, const int* in_sizes, int n_in,
                              void* d_out, int out_size) {
    const float* x       = (const float*)d_in[0];
    const float* conv1_w = (const float*)d_in[1];
    const float* conv1_b = (const float*)d_in[2];
    const float* pconv_w = (const float*)d_in[3];
    const float* pconv_b = (const float*)d_in[4];
    const float* W       = (const float*)d_in[5];
    float* out = (float*)d_out;

    cudaFuncSetAttribute(caps_main, cudaFuncAttributeMaxDynamicSharedMemorySize, SMEM_BYTES);

    reorder_weights<<<(PAIRS * DIMD * 8 + 255) / 256, 256>>>(conv1_w, pconv_w, W);
    caps_main<<<BATCH, 512, SMEM_BYTES>>>(x, conv1_b, pconv_b, out);
}

// round 10
// speedup vs baseline: 5.7059x; 1.1306x over previous
#include <cuda_runtime.h>
#include <cuda_bf16.h>
#include <cuda_fp16.h>
#include <cstdint>

// ---------------- problem constants ----------------
#define BATCH   4096
#define LSEQ    50
#define CIN     128
#define CO1     50
#define K1      9
#define LO1     42
#define KKTOT   1152
#define KCH     128     // conv1 k-chunk (9 chunks == 9 taps)
#define NCH     9
#define CH2     64
#define CI2     42
#define K2      3
#define LO2     48
#define PK      144     // pconv K = 3*48
#define NCAPS   384
#define NO      5
#define DIMD    16
#define PAIRS   1920

// ---------------- smem layout ----------------
// Byte overlay region [0, 61440):
//   phase1: Xh [0,15232)B 56x136h ; WB0 [15232,32640)B 64x136h ; WB1 [32640,50048)B
//   phase2: PWH [0,19456)B 64x152h
//   phase3+: UH2 half2[15360] = [o(5)][dp(8)][c(384)]
// half indices:
#define XH_OFF    0
#define XH_STR    136
#define WB0H      7616
#define WB1H      16320
#define WBSTR     136
#define PWH_OFF   0
#define PWSTR     152
#define HPH_OFF   30720        // halves; 50 x 56
#define HPH_STR   56
// float indices:
#define U_OFF     16760        // 384 x 9
#define U_STRIDE  9
#define BB_OFF    20216
#define CC_OFF    22136
#define S_OFF     24056
#define SC_OFF    24136
#define V_OFF     24144
#define SMEM_FLOATS 24224
#define SMEM_BYTES  (SMEM_FLOATS * 4)

// device-global scratch
__device__ __half g_w16[NCH * 64 * WBSTR];     // conv1 w: [chunk(=tap)][co 64][136h]
__device__ __half g_pw16[CH2 * PWSTR];         // pconv w: [ch][152h]
__device__ __half g_Wt[PAIRS * DIMD * 8];      // routing W transposed [p>>5][d][p&31][8]

__device__ __forceinline__ void mma_f16(float c[4], unsigned a0, unsigned a1,
                                        unsigned a2, unsigned a3,
                                        unsigned b0, unsigned b1) {
    asm volatile(
        "mma.sync.aligned.m16n8k16.row.col.f32.f16.f16.f32 "
        "{%0,%1,%2,%3}, {%4,%5,%6,%7}, {%8,%9}, {%0,%1,%2,%3};"
        : "+f"(c[0]), "+f"(c[1]), "+f"(c[2]), "+f"(c[3])
        : "r"(a0), "r"(a1), "r"(a2), "r"(a3), "r"(b0), "r"(b1));
}

__device__ __forceinline__ void ldsm_x4(unsigned &r0, unsigned &r1,
                                        unsigned &r2, unsigned &r3, unsigned addr) {
    asm volatile("ldmatrix.sync.aligned.m8n8.x4.shared.b16 {%0,%1,%2,%3}, [%4];"
                 : "=r"(r0), "=r"(r1), "=r"(r2), "=r"(r3) : "r"(addr));
}

__device__ __forceinline__ void cp16(unsigned smem_addr, const void* gptr) {
    asm volatile("cp.async.cg.shared.global [%0], [%1], 16;"
                 :: "r"(smem_addr), "l"(gptr));
}
#define CP_COMMIT() asm volatile("cp.async.commit_group;")
#define CP_WAIT(n)  asm volatile("cp.async.wait_group %0;" :: "n"(n))

// ---------------- prologue: weight reorder / convert ----------------
__global__ void reorder_weights(const float* __restrict__ w1,
                                const float* __restrict__ w2,
                                const float* __restrict__ W) {
    int i = blockIdx.x * 256 + threadIdx.x;
    if (i < NCH * 64 * WBSTR) {
        int ch = i / (64 * WBSTR);               // tap index
        int r  = i % (64 * WBSTR);
        int co = r / WBSTR, j = r % WBSTR;       // j = ci (0..127), pad to 136
        float v = 0.f;
        if (j < 128 && co < CO1)
            v = w1[co * KKTOT + j * K1 + ch];
        g_w16[i] = __float2half(v);
    }
    if (i < CH2 * PWSTR) {
        int chn = i / PWSTR, kk = i % PWSTR;
        float v = 0.f;
        if (kk < PK) {
            int kb = kk / 48, ci = kk % 48;
            if (ci < CI2)
                v = w2[chn * (CI2 * K2) + ci * K2 + kb];
        }
        g_pw16[i] = __float2half(v);
    }
    if (i < PAIRS * DIMD * 8) {
        int e  = i & 7;
        int t  = i >> 3;
        int ln = t & 31;
        int t2 = t >> 5;
        int d  = t2 & 15;
        int pg = t2 >> 4;
        int p  = pg * 32 + ln;
        g_Wt[i] = __float2half(W[(p * 16 + d) * 8 + e]);
    }
}

// ---------------- fused main kernel: 1 block = 1 sample, 2 blocks/SM ----------------
__global__ __launch_bounds__(512, 2)
void caps_main(const float* __restrict__ x,
               const float* __restrict__ c1b,
               const float* __restrict__ p2b,
               float* __restrict__ out) {
    extern __shared__ float S[];
    __half*  Sh  = (__half*)S;
    __half2* Sh2 = (__half2*)S;
    const int b    = blockIdx.x;
    const int tid  = threadIdx.x;
    const int lane = tid & 31;
    const int warp = tid >> 5;
    const unsigned smem_u32 = (unsigned)__cvta_generic_to_shared(S);

    // ldmatrix lane selectors
    const int aRowSel = (lane & 7) + ((lane >> 3) & 1) * 8;   // A: row-in-16
    const int aColSel = (lane >> 4) * 8;                      // A: k-half offset
    const int bRowSel = (lane & 7) + (lane >> 4) * 8;         // B: n-row-in-16
    const int bColSel = ((lane >> 3) & 1) * 8;                // B: k-half offset

    // ---- phase 0: cp.async conv chunk 0, stage x->fp16, zero scratch ----
    {
        const uint4* src = (const uint4*)g_w16;   // chunk = 1088 x 16B
        #pragma unroll
        for (int j = 0; j < 3; j++) {
            int i = tid + j * 512;
            if (i < 1088) cp16(smem_u32 + WB0H * 2 + i * 16, src + i);
        }
        CP_COMMIT();
    }
    const float4* xb = (const float4*)(x + (size_t)b * (LSEQ * CIN));
    for (int i = tid; i < (LSEQ * CIN) / 4; i += 512) {
        float4 v = __ldg(xb + i);
        __half2 h0 = __floats2half2_rn(v.x, v.y);
        __half2 h1 = __floats2half2_rn(v.z, v.w);
        int l = i >> 5, c4 = i & 31;
        uint2 pk;
        pk.x = *(unsigned*)&h0; pk.y = *(unsigned*)&h1;
        *(uint2*)&Sh[XH_OFF + l * XH_STR + c4 * 4] = pk;
    }
    for (int i = tid; i < (6 * XH_STR) / 2; i += 512)
        *(unsigned*)&Sh[XH_OFF + 50 * XH_STR + i * 2] = 0u;
    for (int i = tid; i < (CO1 * HPH_STR) / 2; i += 512)
        *(unsigned*)&Sh[HPH_OFF + i * 2] = 0u;
    for (int i = tid; i < PAIRS; i += 512) S[BB_OFF + i] = 0.f;

    // ---- phase 1: conv1 fp16 mma + ldmatrix: C[l(48), co(64)], 9 chunks ----
    const int mt  = warp >> 2;
    const int ntg = warp & 3;
    const int gID = lane >> 2;
    const int tig = lane & 3;
    float acc0[4] = {0, 0, 0, 0};
    float acc1[4] = {0, 0, 0, 0};

    for (int ch = 0; ch < NCH; ch++) {
        __syncthreads();
        if (ch + 1 < NCH) {
            const uint4* src = (const uint4*)g_w16 + (ch + 1) * 1088;
            int wbh = ((ch + 1) & 1) ? WB1H : WB0H;
            #pragma unroll
            for (int j = 0; j < 3; j++) {
                int i = tid + j * 512;
                if (i < 1088) cp16(smem_u32 + wbh * 2 + i * 16, src + i);
            }
            CP_COMMIT();
            CP_WAIT(1);
        } else {
            CP_WAIT(0);
        }
        __syncthreads();
        if (warp < 12) {
            const int wbh = (ch & 1) ? WB1H : WB0H;
            // kh (x row offset) == ch; cb = ks*16 within chunk
            unsigned aBase = smem_u32 +
                2 * (XH_OFF + (mt * 16 + aRowSel + ch) * XH_STR + aColSel);
            unsigned bBase = smem_u32 +
                2 * (wbh + (ntg * 16 + bRowSel) * WBSTR + bColSel);
            #pragma unroll
            for (int ks = 0; ks < KCH / 16; ks++) {
                unsigned a0, a1, a2, a3, b0, b1, b2, b3;
                ldsm_x4(a0, a1, a2, a3, aBase + ks * 32);
                ldsm_x4(b0, b1, b2, b3, bBase + ks * 32);
                mma_f16(acc0, a0, a1, a2, a3, b0, b1);
                mma_f16(acc1, a0, a1, a2, a3, b2, b3);
            }
        }
    }
    __syncthreads();
    // epilogue: bias + relu -> HpH[co][l] (fp16)
    if (warp < 12) {
        int m_lo = mt * 16 + gID, m_hi = m_lo + 8;
        #pragma unroll
        for (int t = 0; t < 2; t++) {
            float* a = (t == 0) ? acc0 : acc1;
            #pragma unroll
            for (int q = 0; q < 2; q++) {
                int n = ntg * 16 + t * 8 + 2 * tig + q;
                if (n < CO1) {
                    float bias = __ldg(&c1b[n]);
                    if (m_lo < LO1)
                        Sh[HPH_OFF + n * HPH_STR + m_lo] = __float2half(fmaxf(a[q] + bias, 0.f));
                    if (m_hi < LO1)
                        Sh[HPH_OFF + n * HPH_STR + m_hi] = __float2half(fmaxf(a[q + 2] + bias, 0.f));
                }
            }
        }
    }
    __syncthreads();

    // ---- phase 2: pconv fp16 mma + ldmatrix: C[pos(48), ch(64)], K=144 ----
    for (int i = tid; i < (CH2 * PWSTR) / 8; i += 512) {
        uint4 v = __ldg((const uint4*)g_pw16 + i);
        *(uint4*)&Sh[PWH_OFF + i * 8] = v;
    }
    __syncthreads();
    {
        float pacc0[4] = {0, 0, 0, 0};
        float pacc1[4] = {0, 0, 0, 0};
        if (warp < 12) {
            unsigned bBase = smem_u32 +
                2 * (PWH_OFF + (ntg * 16 + bRowSel) * PWSTR + bColSel);
            #pragma unroll
            for (int ks = 0; ks < PK / 16; ks++) {
                int kb = (ks * 16) / 48, cb = (ks * 16) % 48;
                unsigned aAddr = smem_u32 +
                    2 * (HPH_OFF + (mt * 16 + aRowSel + kb) * HPH_STR + cb + aColSel);
                unsigned a0, a1, a2, a3, b0, b1, b2, b3;
                ldsm_x4(a0, a1, a2, a3, aAddr);
                ldsm_x4(b0, b1, b2, b3, bBase + ks * 32);
                mma_f16(pacc0, a0, a1, a2, a3, b0, b1);
                mma_f16(pacc1, a0, a1, a2, a3, b2, b3);
            }
            int m_lo = mt * 16 + gID, m_hi = m_lo + 8;
            #pragma unroll
            for (int t = 0; t < 2; t++) {
                float* a = (t == 0) ? pacc0 : pacc1;
                #pragma unroll
                for (int q = 0; q < 2; q++) {
                    int n = ntg * 16 + t * 8 + 2 * tig + q;
                    float bias = __ldg(&p2b[n]);
                    int lin0 = n * LO2 + m_lo;
                    int lin1 = n * LO2 + m_hi;
                    S[U_OFF + (lin0 >> 3) * U_STRIDE + (lin0 & 7)] = a[q] + bias;
                    S[U_OFF + (lin1 >> 3) * U_STRIDE + (lin1 & 7)] = a[q + 2] + bias;
                }
            }
        }
    }
    __syncthreads();
    if (tid < NCAPS) {
        float vv[8], sq = 0.f;
        #pragma unroll
        for (int i = 0; i < 8; i++) { vv[i] = S[U_OFF + tid * U_STRIDE + i]; sq += vv[i] * vv[i]; }
        float sc = sq / ((1.f + sq) * (sqrtf(sq) + 1e-8f));
        #pragma unroll
        for (int i = 0; i < 8; i++) S[U_OFF + tid * U_STRIDE + i] = vv[i] * sc;
    }
    __syncthreads();

    // ---- phase 3: u_hat -> UH2[o][dp][c] half2 ----
    for (int p = tid; p < PAIRS; p += 512) {
        int c = p % NCAPS;
        int o = p / NCAPS;
        float u8[8];
        #pragma unroll
        for (int i = 0; i < 8; i++) u8[i] = S[U_OFF + c * U_STRIDE + i];
        const uint4* wp = (const uint4*)g_Wt + ((p >> 5) * 16) * 32 + (p & 31);
        #pragma unroll 4
        for (int dp = 0; dp < 8; dp++) {
            uint4 r0 = __ldg(wp + (2 * dp) * 32);
            uint4 r1 = __ldg(wp + (2 * dp + 1) * 32);
            float2 f0 = __half22float2(*(__half2*)&r0.x);
            float2 f1 = __half22float2(*(__half2*)&r0.y);
            float2 f2 = __half22float2(*(__half2*)&r0.z);
            float2 f3 = __half22float2(*(__half2*)&r0.w);
            float s0 = f0.x * u8[0] + f0.y * u8[1] + f1.x * u8[2] + f1.y * u8[3]
                     + f2.x * u8[4] + f2.y * u8[5] + f3.x * u8[6] + f3.y * u8[7];
            f0 = __half22float2(*(__half2*)&r1.x);
            f1 = __half22float2(*(__half2*)&r1.y);
            f2 = __half22float2(*(__half2*)&r1.z);
            f3 = __half22float2(*(__half2*)&r1.w);
            float s1 = f0.x * u8[0] + f0.y * u8[1] + f1.x * u8[2] + f1.y * u8[3]
                     + f2.x * u8[4] + f2.y * u8[5] + f3.x * u8[6] + f3.y * u8[7];
            Sh2[(o * 8 + dp) * NCAPS + c] = __floats2half2_rn(s0, s1);
        }
    }
    __syncthreads();

    // ---- phase 4: dynamic routing (it=0 softmax skipped: c == 0.2) ----
    for (int it = 0; it < 3; it++) {
        if (it) {
            if (tid < NCAPS) {
                float bv[NO], m = -1e30f;
                #pragma unroll
                for (int o = 0; o < NO; o++) { bv[o] = S[BB_OFF + o * NCAPS + tid]; m = fmaxf(m, bv[o]); }
                float sum = 0.f;
                #pragma unroll
                for (int o = 0; o < NO; o++) { bv[o] = expf(bv[o] - m); sum += bv[o]; }
                float inv = 1.f / sum;
                #pragma unroll
                for (int o = 0; o < NO; o++) S[CC_OFF + o * NCAPS + tid] = bv[o] * inv;
            }
            __syncthreads();
        }
        for (int comb = warp; comb < NO * 8; comb += 16) {
            int o = comb >> 3, dp = comb & 7;
            float a0 = 0.f, a1 = 0.f;
            if (it == 0) {
                #pragma unroll 4
                for (int c = lane; c < NCAPS; c += 32) {
                    float2 f = __half22float2(Sh2[(o * 8 + dp) * NCAPS + c]);
                    a0 += f.x;
                    a1 += f.y;
                }
                a0 *= 0.2f; a1 *= 0.2f;
            } else {
                #pragma unroll 4
                for (int c = lane; c < NCAPS; c += 32) {
                    float cc = S[CC_OFF + o * NCAPS + c];
                    float2 f = __half22float2(Sh2[(o * 8 + dp) * NCAPS + c]);
                    a0 += cc * f.x;
                    a1 += cc * f.y;
                }
            }
            #pragma unroll
            for (int off = 16; off; off >>= 1) {
                a0 += __shfl_xor_sync(0xffffffffu, a0, off);
                a1 += __shfl_xor_sync(0xffffffffu, a1, off);
            }
            if (lane == 0) {
                S[S_OFF + o * DIMD + 2 * dp]     = a0;
                S[S_OFF + o * DIMD + 2 * dp + 1] = a1;
            }
        }
        __syncthreads();
        if (tid < NO) {
            float sq = 0.f;
            #pragma unroll
            for (int d = 0; d < DIMD; d++) { float t = S[S_OFF + tid * DIMD + d]; sq += t * t; }
            S[SC_OFF + tid] = sq / ((1.f + sq) * (sqrtf(sq) + 1e-8f));
        }
        __syncthreads();
        if (it == 2) break;
        if (tid < NO * DIMD) S[V_OFF + tid] = S[S_OFF + tid] * S[SC_OFF + (tid >> 4)];
        __syncthreads();
        for (int p = tid; p < PAIRS; p += 512) {
            int o = p / NCAPS;
            int c = p % NCAPS;
            float a = 0.f;
            #pragma unroll
            for (int j = 0; j < 8; j++) {
                float2 f = __half22float2(Sh2[(o * 8 + j) * NCAPS + c]);
                a += f.x * S[V_OFF + o * DIMD + 2 * j] + f.y * S[V_OFF + o * DIMD + 2 * j + 1];
            }
            S[BB_OFF + p] += a;
        }
        __syncthreads();
    }
    if (tid < NO * DIMD)
        out[(size_t)b * (NO * DIMD) + tid] = S[S_OFF + tid] * S[SC_OFF + (tid >> 4)];
}

// ---------------- launch ----------------
extern "C" void kernel_launch(void* const* d_in, const int* in_sizes, int n_in,
                              void* d_out, int out_size) {
    const float* x       = (const float*)d_in[0];
    const float* conv1_w = (const float*)d_in[1];
    const float* conv1_b = (const float*)d_in[2];
    const float* pconv_w = (const float*)d_in[3];
    const float* pconv_b = (const float*)d_in[4];
    const float* W       = (const float*)d_in[5];
    float* out = (float*)d_out;

    cudaFuncSetAttribute(caps_main, cudaFuncAttributeMaxDynamicSharedMemorySize, SMEM_BYTES);

    reorder_weights<<<(PAIRS * DIMD * 8 + 255) / 256, 256>>>(conv1_w, pconv_w, W);
    caps_main<<<BATCH, 512, SMEM_BYTES>>>(x, conv1_b, pconv_b, out);
}